// round 1
// baseline (speedup 1.0000x reference)
#include <cuda_runtime.h>
#include <math.h>

// ---------------- problem dims ----------------
#define BQ   128
#define SQ   32
#define INQ  512
#define HQ   1024
#define OUTQ 512
#define NQ   16384
#define WQ   128
#define CQ   899          // controller output size
#define K1   1664         // IN + W + H (concat input to fused LSTM gemm)
#define G4   4096         // 4*H
#define HR   516          // packed head rows: 128 rk + 1 rb + 1 rg + 128 wk + 1 wb + 1 wg + 128 er + 128 ad
#define NCHUNK 256        // split-K chunks for rv

// ---------------- device scratch (allocation-free: __device__ globals) ----------------
__device__ float sc_mem[NQ * WQ];          // working memory (8.4 MB)
__device__ float sc_Wcat[G4 * K1];         // [Wih | Whh] packed (27 MB)
__device__ float sc_bg[G4];                // bih + bhh
__device__ float sc_HW[HR * CQ];           // packed head weights
__device__ float sc_Hb[HR];                // packed head biases
__device__ float sc_h[BQ * HQ];
__device__ float sc_c[BQ * HQ];
__device__ float sc_rv[BQ * WQ];
__device__ float sc_rw[BQ * NQ];           // read weights (8.4 MB)
__device__ float sc_ww[BQ * NQ];           // write weights (8.4 MB)
__device__ float sc_in[BQ * K1];
__device__ float sc_g[BQ * G4];
__device__ float sc_co[BQ * CQ];
__device__ float sc_heads[BQ * HR];
__device__ float sc_keys[2 * BQ * WQ];     // normalized read+write keys (256 x 128)
__device__ float sc_beta[2 * BQ];
__device__ float sc_gamma[2 * BQ];
__device__ float sc_er[BQ * WQ];
__device__ float sc_ad[BQ * WQ];
__device__ float sc_sim[2 * BQ * NQ];      // similarities (16.8 MB)
__device__ float sc_invn[NQ];              // 1/||mem row||
__device__ float sc_rvpart[NCHUNK * BQ * WQ]; // split-K partials (16.8 MB)

// ---------------- helpers ----------------
__device__ __forceinline__ float sigmoidf_(float x) { return 1.0f / (1.0f + expf(-x)); }
__device__ __forceinline__ float softplusf_(float x) { return x > 20.0f ? x : log1pf(expf(x)); }

// ---------------- prologue kernels ----------------
__global__ void k_build_wcat(const float* __restrict__ Wih, const float* __restrict__ Whh) {
    long long idx = (long long)blockIdx.x * blockDim.x + threadIdx.x;
    if (idx >= (long long)G4 * K1) return;
    int r = (int)(idx / K1), k = (int)(idx % K1);
    sc_Wcat[idx] = (k < INQ + WQ) ? Wih[r * (INQ + WQ) + k] : Whh[r * HQ + (k - INQ - WQ)];
}

__global__ void k_build_bg(const float* __restrict__ bih, const float* __restrict__ bhh) {
    int i = blockIdx.x * blockDim.x + threadIdx.x;
    if (i < G4) sc_bg[i] = bih[i] + bhh[i];
}

__global__ void k_build_hw(const float* rkW, const float* rbW, const float* rgW,
                           const float* wkW, const float* wbW, const float* wgW,
                           const float* erW, const float* adW,
                           const float* rkb, const float* rbb, const float* rgb,
                           const float* wkb, const float* wbb, const float* wgb,
                           const float* erb, const float* adb) {
    int idx = blockIdx.x * blockDim.x + threadIdx.x;
    if (idx >= HR * CQ) return;
    int r = idx / CQ, k = idx % CQ;
    float wv, bv;
    if (r < 128)      { wv = rkW[r * CQ + k];         bv = rkb[r]; }
    else if (r == 128){ wv = rbW[k];                  bv = rbb[0]; }
    else if (r == 129){ wv = rgW[k];                  bv = rgb[0]; }
    else if (r < 258) { wv = wkW[(r - 130) * CQ + k]; bv = wkb[r - 130]; }
    else if (r == 258){ wv = wbW[k];                  bv = wbb[0]; }
    else if (r == 259){ wv = wgW[k];                  bv = wgb[0]; }
    else if (r < 388) { wv = erW[(r - 260) * CQ + k]; bv = erb[r - 260]; }
    else              { wv = adW[(r - 388) * CQ + k]; bv = adb[r - 388]; }
    sc_HW[idx] = wv;
    if (k == 0) sc_Hb[r] = bv;
}

__global__ void k_init(const float* __restrict__ memory) {
    long long i = (long long)blockIdx.x * blockDim.x + threadIdx.x;
    long long tot = (long long)NQ * WQ;   // 2,097,152 == BQ*NQ
    if (i < tot) {
        sc_mem[i] = memory[i];
        sc_rw[i]  = 1.0f / (float)NQ;
    }
    if (i < BQ * HQ) { sc_h[i] = 0.0f; sc_c[i] = 0.0f; }
    if (i < BQ * WQ) sc_rv[i] = 0.0f;
}

// ---------------- per-step kernels ----------------
__global__ void k_build_in(const float* __restrict__ x, int s) {
    int idx = blockIdx.x * blockDim.x + threadIdx.x;
    if (idx >= BQ * K1) return;
    int b = idx / K1, k = idx % K1;
    float v;
    if (k < INQ)            v = x[((long long)b * SQ + s) * INQ + k];
    else if (k < INQ + WQ)  v = sc_rv[b * WQ + (k - INQ)];
    else                    v = sc_h[b * HQ + (k - INQ - WQ)];
    sc_in[idx] = v;
}

// generic C[M,N] = A[M,K] @ B[N,K]^T (+bias[n]) (*colscale[n]); 64x64 tile, 4x4/thread
__global__ __launch_bounds__(256) void sgemm_abT(
    const float* __restrict__ A, int lda,
    const float* __restrict__ B, int ldb,
    float* __restrict__ C, int ldc,
    const float* __restrict__ bias,
    const float* __restrict__ colscale,
    int M, int N, int K)
{
    __shared__ float As[16][64];
    __shared__ float Bs[16][64];
    int tid = threadIdx.x;
    int m0 = blockIdx.y * 64, n0 = blockIdx.x * 64;
    int txm = tid & 15, txn = tid >> 4;
    float acc[4][4] = {};
    int rowA = tid >> 2;               // 0..63
    int kkb  = (tid & 3) * 4;          // 0,4,8,12
    for (int k0 = 0; k0 < K; k0 += 16) {
        int gm = m0 + rowA, gn = n0 + rowA;
        #pragma unroll
        for (int i = 0; i < 4; i++) {
            int kk = kkb + i;
            float va = 0.f, vb = 0.f;
            if (gm < M && (k0 + kk) < K) va = A[(long long)gm * lda + k0 + kk];
            if (gn < N && (k0 + kk) < K) vb = B[(long long)gn * ldb + k0 + kk];
            As[kk][rowA] = va;
            Bs[kk][rowA] = vb;
        }
        __syncthreads();
        #pragma unroll
        for (int kk = 0; kk < 16; kk++) {
            float a[4], b[4];
            #pragma unroll
            for (int i = 0; i < 4; i++) a[i] = As[kk][txm * 4 + i];
            #pragma unroll
            for (int j = 0; j < 4; j++) b[j] = Bs[kk][txn * 4 + j];
            #pragma unroll
            for (int i = 0; i < 4; i++)
                #pragma unroll
                for (int j = 0; j < 4; j++)
                    acc[i][j] = fmaf(a[i], b[j], acc[i][j]);
        }
        __syncthreads();
    }
    #pragma unroll
    for (int i = 0; i < 4; i++) {
        int m = m0 + txm * 4 + i;
        if (m >= M) continue;
        #pragma unroll
        for (int j = 0; j < 4; j++) {
            int n = n0 + txn * 4 + j;
            if (n >= N) continue;
            float v = acc[i][j];
            if (bias)     v += bias[n];
            if (colscale) v *= colscale[n];
            C[(long long)m * ldc + n] = v;
        }
    }
}

__global__ void k_gates() {
    int idx = blockIdx.x * blockDim.x + threadIdx.x;
    if (idx >= BQ * HQ) return;
    int b = idx >> 10, j = idx & 1023;
    const float* g = sc_g + (long long)b * G4;
    float i_ = g[j], f_ = g[j + HQ], gg = g[j + 2 * HQ], o_ = g[j + 3 * HQ];
    float c = sigmoidf_(f_) * sc_c[idx] + sigmoidf_(i_) * tanhf(gg);
    sc_c[idx] = c;
    sc_h[idx] = sigmoidf_(o_) * tanhf(c);
}

__device__ __forceinline__ float blockSum128(float v, float* sh) {
    #pragma unroll
    for (int o = 16; o; o >>= 1) v += __shfl_xor_sync(0xffffffffu, v, o);
    int wp = threadIdx.x >> 5;
    if ((threadIdx.x & 31) == 0) sh[wp] = v;
    __syncthreads();
    float r = sh[0] + sh[1] + sh[2] + sh[3];
    __syncthreads();
    return r;
}

__global__ __launch_bounds__(128) void k_headproc() {
    __shared__ float sh[4];
    int b = blockIdx.x, w = threadIdx.x;
    const float* hd = sc_heads + b * HR;
    float rk = hd[w], wk = hd[130 + w];
    float nr2 = blockSum128(rk * rk, sh);
    float nw2 = blockSum128(wk * wk, sh);
    sc_keys[b * WQ + w]            = rk / fmaxf(sqrtf(nr2), 1e-12f);
    sc_keys[(128 + b) * WQ + w]    = wk / fmaxf(sqrtf(nw2), 1e-12f);
    if (w == 0) {
        sc_beta[b]        = softplusf_(hd[128]);
        sc_gamma[b]       = 1.0f + softplusf_(hd[129]);
        sc_beta[128 + b]  = softplusf_(hd[258]);
        sc_gamma[128 + b] = 1.0f + softplusf_(hd[259]);
    }
    sc_er[b * WQ + w] = sigmoidf_(hd[260 + w]);
    sc_ad[b * WQ + w] = tanhf(hd[388 + w]);
}

__global__ void k_invnorm() {
    int row = blockIdx.x * (blockDim.x >> 5) + (threadIdx.x >> 5);
    int lane = threadIdx.x & 31;
    if (row >= NQ) return;
    const float* r = sc_mem + (long long)row * WQ;
    float s = 0.f;
    #pragma unroll
    for (int i = 0; i < 4; i++) { float v = r[lane + 32 * i]; s += v * v; }
    #pragma unroll
    for (int o = 16; o; o >>= 1) s += __shfl_xor_sync(0xffffffffu, s, o);
    if (lane == 0) sc_invn[row] = 1.0f / fmaxf(sqrtf(s), 1e-12f);
}

__global__ __launch_bounds__(256) void k_softmax() {
    __shared__ float sh[8];
    __shared__ float bc[2];
    int q = blockIdx.x, tid = threadIdx.x;
    float beta = sc_beta[q], gamma = sc_gamma[q];
    float* row = sc_sim + (long long)q * NQ;
    // pass 1: max
    float mx = -1e30f;
    for (int n = tid; n < NQ; n += 256) mx = fmaxf(mx, row[n]);
    #pragma unroll
    for (int o = 16; o; o >>= 1) mx = fmaxf(mx, __shfl_xor_sync(0xffffffffu, mx, o));
    if ((tid & 31) == 0) sh[tid >> 5] = mx;
    __syncthreads();
    if (tid == 0) {
        float m = sh[0];
        #pragma unroll
        for (int i = 1; i < 8; i++) m = fmaxf(m, sh[i]);
        bc[0] = m;
    }
    __syncthreads();
    mx = bc[0];
    __syncthreads();
    // pass 2: exp + sum (store p back into row)
    float s = 0.f;
    for (int n = tid; n < NQ; n += 256) {
        float p = expf(beta * (row[n] - mx));
        row[n] = p;
        s += p;
    }
    #pragma unroll
    for (int o = 16; o; o >>= 1) s += __shfl_xor_sync(0xffffffffu, s, o);
    if ((tid & 31) == 0) sh[tid >> 5] = s;
    __syncthreads();
    if (tid == 0) {
        float t = 0.f;
        #pragma unroll
        for (int i = 0; i < 8; i++) t += sh[i];
        bc[1] = 1.0f / t;
    }
    __syncthreads();
    float inv = bc[1];
    // pass 3: interpolate
    if (q < 128) {
        float* rw = sc_rw + (long long)q * NQ;
        for (int n = tid; n < NQ; n += 256) {
            float wgt = row[n] * inv;
            rw[n] = gamma * wgt + (1.0f - gamma) * rw[n];
        }
    } else {
        float* ww = sc_ww + (long long)(q - 128) * NQ;
        float u = (1.0f - gamma) * (1.0f / (float)NQ);
        for (int n = tid; n < NQ; n += 256) {
            float wgt = row[n] * inv;
            ww[n] = gamma * wgt + u;
        }
    }
}

// mem[n,w] = mem[n,w]*(1 - sum_b ww[b,n]er[b,w]) + sum_b ww[b,n]ad[b,w]
__global__ __launch_bounds__(256) void k_memupdate() {
    __shared__ float sw[16][64], se[16][64], sa[16][64];
    int tid = threadIdx.x;
    int n0 = blockIdx.x * 64, w0 = blockIdx.y * 64;
    int txn = tid & 15, txw = tid >> 4;
    float ae[4][4] = {}, aa[4][4] = {};
    int kk = tid >> 4;
    int cb = (tid & 15) * 4;
    for (int b0 = 0; b0 < BQ; b0 += 16) {
        #pragma unroll
        for (int i = 0; i < 4; i++) {
            sw[kk][cb + i] = sc_ww[(long long)(b0 + kk) * NQ + n0 + cb + i];
            se[kk][cb + i] = sc_er[(b0 + kk) * WQ + w0 + cb + i];
            sa[kk][cb + i] = sc_ad[(b0 + kk) * WQ + w0 + cb + i];
        }
        __syncthreads();
        #pragma unroll
        for (int k = 0; k < 16; k++) {
            float wv[4], ev[4], av[4];
            #pragma unroll
            for (int i = 0; i < 4; i++) wv[i] = sw[k][txn * 4 + i];
            #pragma unroll
            for (int j = 0; j < 4; j++) { ev[j] = se[k][txw * 4 + j]; av[j] = sa[k][txw * 4 + j]; }
            #pragma unroll
            for (int i = 0; i < 4; i++)
                #pragma unroll
                for (int j = 0; j < 4; j++) {
                    ae[i][j] = fmaf(wv[i], ev[j], ae[i][j]);
                    aa[i][j] = fmaf(wv[i], av[j], aa[i][j]);
                }
        }
        __syncthreads();
    }
    #pragma unroll
    for (int i = 0; i < 4; i++) {
        int n = n0 + txn * 4 + i;
        #pragma unroll
        for (int j = 0; j < 4; j++) {
            int w = w0 + txw * 4 + j;
            long long idx = (long long)n * WQ + w;
            sc_mem[idx] = sc_mem[idx] * (1.0f - ae[i][j]) + aa[i][j];
        }
    }
}

// rv split-K: each block handles K-chunk of 64 over all 128x128 outputs
__global__ __launch_bounds__(256) void k_rvpart() {
    __shared__ float sr[16][128];  // [k][b]
    __shared__ float sm[16][128];  // [k][w]
    int tid = threadIdx.x;
    int kbase = blockIdx.x * 64;
    int txb = tid & 15, txw = tid >> 4;
    float acc[8][8] = {};
    for (int kk0 = 0; kk0 < 64; kk0 += 16) {
        #pragma unroll
        for (int i = 0; i < 8; i++) {
            int l = tid * 8 + i;
            int bb = l >> 4, k = l & 15;
            sr[k][bb] = sc_rw[(long long)bb * NQ + kbase + kk0 + k];
            int k2 = l >> 7, ww_ = l & 127;
            sm[k2][ww_] = sc_mem[(long long)(kbase + kk0 + k2) * WQ + ww_];
        }
        __syncthreads();
        #pragma unroll
        for (int k = 0; k < 16; k++) {
            float rb[8], mw[8];
            #pragma unroll
            for (int i = 0; i < 8; i++) rb[i] = sr[k][txb * 8 + i];
            #pragma unroll
            for (int j = 0; j < 8; j++) mw[j] = sm[k][txw * 8 + j];
            #pragma unroll
            for (int i = 0; i < 8; i++)
                #pragma unroll
                for (int j = 0; j < 8; j++)
                    acc[i][j] = fmaf(rb[i], mw[j], acc[i][j]);
        }
        __syncthreads();
    }
    float* dst = sc_rvpart + (long long)blockIdx.x * BQ * WQ;
    #pragma unroll
    for (int i = 0; i < 8; i++)
        #pragma unroll
        for (int j = 0; j < 8; j++)
            dst[(txb * 8 + i) * WQ + txw * 8 + j] = acc[i][j];
}

__global__ void k_rvreduce() {
    int idx = blockIdx.x * blockDim.x + threadIdx.x;
    if (idx >= BQ * WQ) return;
    float s = 0.f;
    for (int c = 0; c < NCHUNK; c++) s += sc_rvpart[(long long)c * BQ * WQ + idx];
    sc_rv[idx] = s;
}

// ---------------- host launcher ----------------
extern "C" void kernel_launch(void* const* d_in, const int* in_sizes, int n_in,
                              void* d_out, int out_size) {
    const float* x      = (const float*)d_in[0];
    const float* memory = (const float*)d_in[1];
    const float* Wih    = (const float*)d_in[2];
    const float* Whh    = (const float*)d_in[3];
    const float* bih    = (const float*)d_in[4];
    const float* bhh    = (const float*)d_in[5];
    const float* Wout   = (const float*)d_in[6];
    const float* bout   = (const float*)d_in[7];
    const float* rkW    = (const float*)d_in[8];
    const float* rkb    = (const float*)d_in[9];
    const float* rbW    = (const float*)d_in[10];
    const float* rbb    = (const float*)d_in[11];
    const float* rgW    = (const float*)d_in[12];
    const float* rgb    = (const float*)d_in[13];
    const float* wkW    = (const float*)d_in[14];
    const float* wkb    = (const float*)d_in[15];
    const float* wbW    = (const float*)d_in[16];
    const float* wbb    = (const float*)d_in[17];
    const float* wgW    = (const float*)d_in[18];
    const float* wgb    = (const float*)d_in[19];
    const float* erW    = (const float*)d_in[20];
    const float* erb    = (const float*)d_in[21];
    const float* adW    = (const float*)d_in[22];
    const float* adb    = (const float*)d_in[23];
    const float* pW     = (const float*)d_in[24];
    const float* pb     = (const float*)d_in[25];
    float* out          = (float*)d_out;

    float *pin, *pWcat, *pbg, *pg, *ph, *pco, *pHW, *pHb, *pheads, *pkeys, *pmem, *psim, *pinvn;
    cudaGetSymbolAddress((void**)&pin,    sc_in);
    cudaGetSymbolAddress((void**)&pWcat,  sc_Wcat);
    cudaGetSymbolAddress((void**)&pbg,    sc_bg);
    cudaGetSymbolAddress((void**)&pg,     sc_g);
    cudaGetSymbolAddress((void**)&ph,     sc_h);
    cudaGetSymbolAddress((void**)&pco,    sc_co);
    cudaGetSymbolAddress((void**)&pHW,    sc_HW);
    cudaGetSymbolAddress((void**)&pHb,    sc_Hb);
    cudaGetSymbolAddress((void**)&pheads, sc_heads);
    cudaGetSymbolAddress((void**)&pkeys,  sc_keys);
    cudaGetSymbolAddress((void**)&pmem,   sc_mem);
    cudaGetSymbolAddress((void**)&psim,   sc_sim);
    cudaGetSymbolAddress((void**)&pinvn,  sc_invn);

    // prologue: pack weights, init state
    k_build_wcat<<<(int)(((long long)G4 * K1 + 255) / 256), 256>>>(Wih, Whh);
    k_build_bg<<<(G4 + 255) / 256, 256>>>(bih, bhh);
    k_build_hw<<<(HR * CQ + 255) / 256, 256>>>(rkW, rbW, rgW, wkW, wbW, wgW, erW, adW,
                                               rkb, rbb, rgb, wkb, wbb, wgb, erb, adb);
    k_init<<<(int)(((long long)NQ * WQ + 511) / 512), 512>>>(memory);

    for (int s = 0; s < SQ; s++) {
        // 1. concat input [x_t, rv, h]
        k_build_in<<<(BQ * K1 + 255) / 256, 256>>>(x, s);
        // 2. LSTM gate GEMM: g = in @ Wcat^T + (bih+bhh)   [128,4096] K=1664
        sgemm_abT<<<dim3(G4 / 64, BQ / 64), 256>>>(pin, K1, pWcat, K1, pg, G4, pbg, nullptr, BQ, G4, K1);
        // 3. gate nonlinearity -> c, h
        k_gates<<<(BQ * HQ + 255) / 256, 256>>>();
        // 4. controller output: co = h @ Wout^T + bout   [128,899] K=1024
        sgemm_abT<<<dim3((CQ + 63) / 64, BQ / 64), 256>>>(ph, HQ, Wout, HQ, pco, CQ, bout, nullptr, BQ, CQ, HQ);
        // 5. all head projections packed: heads = co @ HW^T + Hb   [128,516] K=899
        sgemm_abT<<<dim3((HR + 63) / 64, BQ / 64), 256>>>(pco, CQ, pHW, CQ, pheads, HR, pHb, nullptr, BQ, HR, CQ);
        // 6. normalize keys, betas/gammas, erase/add vectors
        k_headproc<<<BQ, 128>>>();
        // 7. memory row inverse norms (pre-write memory)
        k_invnorm<<<NQ / 8, 256>>>();
        // 8. cosine similarity: sim = keys_norm @ mem^T * invnorm[n]   [256,16384] K=128
        sgemm_abT<<<dim3(NQ / 64, 256 / 64), 256>>>(pkeys, WQ, pmem, WQ, psim, NQ, nullptr, pinvn, 2 * BQ, NQ, WQ);
        // 9. softmax(beta*sim) + interpolation -> rw, ww
        k_softmax<<<2 * BQ, 256>>>();
        // 10. memory write (erase/add outer products fused with update)
        k_memupdate<<<dim3(NQ / 64, WQ / 64), 256>>>();
        // 11. read: rv = rw @ mem  (split-K 256 chunks + deterministic reduce)
        k_rvpart<<<NCHUNK, 256>>>();
        k_rvreduce<<<(BQ * WQ + 255) / 256, 256>>>();
        // 12. output projection: out[:,s,:] = co[:, :512] @ pW^T + pb
        sgemm_abT<<<dim3(OUTQ / 64, BQ / 64), 256>>>(pco, CQ, pW, OUTQ, out + (long long)s * OUTQ,
                                                     SQ * OUTQ, pb, nullptr, BQ, OUTQ, OUTQ);
    }
}

// round 2
// speedup vs baseline: 1.5078x; 1.5078x over previous
#include <cuda_runtime.h>
#include <math.h>

// ---------------- problem dims ----------------
#define BQ   128
#define SQ   32
#define INQ  512
#define HQ   1024
#define OUTQ 512
#define NQ   16384
#define WQ   128
#define CQ   899          // true controller output size
#define CP   960          // padded controller size (multiple of 64)
#define K1   1664         // IN + W + H (concat input to fused LSTM gemm)
#define G4   4096         // 4*H
#define HRP  576          // padded head rows (516 real)
#define NCHUNK 256        // split-K chunks for rv

// ---------------- device scratch ----------------
__device__ float sc_mem[NQ * WQ];
__device__ float sc_Wcat[G4 * K1];         // gate-interleaved [Wih|Whh]
__device__ float sc_bg[G4];                // interleaved bih+bhh
__device__ float sc_WoutP[CP * HQ];        // padded Wout
__device__ float sc_boutP[CP];
__device__ float sc_HW[HRP * CP];          // packed padded head weights
__device__ float sc_Hb[HRP];
__device__ float sc_hA[BQ * HQ];
__device__ float sc_hB[BQ * HQ];
__device__ float sc_c[BQ * HQ];
__device__ float sc_rv[BQ * WQ];
__device__ float sc_rw[BQ * NQ];
__device__ float sc_ww[BQ * NQ];
__device__ float sc_co[BQ * CP];
__device__ float sc_heads[BQ * HRP];
__device__ float sc_keys[2 * BQ * WQ];
__device__ float sc_beta[2 * BQ];
__device__ float sc_gamma[2 * BQ];
__device__ float sc_er[BQ * WQ];
__device__ float sc_ad[BQ * WQ];
__device__ float sc_sim[2 * BQ * NQ];
__device__ float sc_invn[NQ];
__device__ float sc_rvpart[NCHUNK * BQ * WQ];

// ---------------- helpers ----------------
__device__ __forceinline__ float sigmoidf_(float x) { return 1.0f / (1.0f + expf(-x)); }
__device__ __forceinline__ float softplusf_(float x) { return x > 20.0f ? x : log1pf(expf(x)); }

// ---------------- prologue kernels ----------------
// Gate-interleaved Wcat: dst row r = 4*j + g  <-  src row g*H + j
__global__ void k_build_wcat(const float* __restrict__ Wih, const float* __restrict__ Whh) {
    long long idx = (long long)blockIdx.x * blockDim.x + threadIdx.x;
    if (idx >= (long long)G4 * K1) return;
    int r = (int)(idx / K1), k = (int)(idx % K1);
    int j = r >> 2, g = r & 3;
    int src = g * HQ + j;
    sc_Wcat[idx] = (k < INQ + WQ) ? Wih[src * (INQ + WQ) + k] : Whh[src * HQ + (k - INQ - WQ)];
}

__global__ void k_build_bg(const float* __restrict__ bih, const float* __restrict__ bhh) {
    int r = blockIdx.x * blockDim.x + threadIdx.x;
    if (r >= G4) return;
    int j = r >> 2, g = r & 3;
    int src = g * HQ + j;
    sc_bg[r] = bih[src] + bhh[src];
}

__global__ void k_build_woutp(const float* __restrict__ Wout, const float* __restrict__ bout) {
    long long idx = (long long)blockIdx.x * blockDim.x + threadIdx.x;
    if (idx >= (long long)CP * HQ) return;
    int r = (int)(idx / HQ), k = (int)(idx % HQ);
    sc_WoutP[idx] = (r < CQ) ? Wout[(long long)r * HQ + k] : 0.0f;
    if (k == 0) sc_boutP[r] = (r < CQ) ? bout[r] : 0.0f;
}

__global__ void k_build_hw(const float* rkW, const float* rbW, const float* rgW,
                           const float* wkW, const float* wbW, const float* wgW,
                           const float* erW, const float* adW,
                           const float* rkb, const float* rbb, const float* rgb,
                           const float* wkb, const float* wbb, const float* wgb,
                           const float* erb, const float* adb) {
    int idx = blockIdx.x * blockDim.x + threadIdx.x;
    if (idx >= HRP * CP) return;
    int r = idx / CP, k = idx % CP;
    float wv = 0.0f, bv = 0.0f;
    if (k < CQ && r < 516) {
        if (r < 128)      { wv = rkW[r * CQ + k];         bv = rkb[r]; }
        else if (r == 128){ wv = rbW[k];                  bv = rbb[0]; }
        else if (r == 129){ wv = rgW[k];                  bv = rgb[0]; }
        else if (r < 258) { wv = wkW[(r - 130) * CQ + k]; bv = wkb[r - 130]; }
        else if (r == 258){ wv = wbW[k];                  bv = wbb[0]; }
        else if (r == 259){ wv = wgW[k];                  bv = wgb[0]; }
        else if (r < 388) { wv = erW[(r - 260) * CQ + k]; bv = erb[r - 260]; }
        else              { wv = adW[(r - 388) * CQ + k]; bv = adb[r - 388]; }
    }
    sc_HW[idx] = wv;
    if (k == 0) sc_Hb[r] = bv;
}

__global__ void k_init(const float* __restrict__ memory) {
    long long i = (long long)blockIdx.x * blockDim.x + threadIdx.x;
    long long tot = (long long)NQ * WQ;    // == BQ*NQ
    if (i < tot) {
        sc_mem[i] = memory[i];
        sc_rw[i]  = 1.0f / (float)NQ;
    }
    if (i < BQ * HQ) { sc_hA[i] = 0.0f; sc_hB[i] = 0.0f; sc_c[i] = 0.0f; }
    if (i < BQ * WQ) sc_rv[i] = 0.0f;
}

// ---------------- fused LSTM: concat-load + GEMM + gates ----------------
// out tile 64(m=batch) x 64(n=4 gates x 16 units); epilogue computes c,h.
__global__ __launch_bounds__(256) void k_lstm(const float* __restrict__ x, int s,
                                              const float* __restrict__ hprev,
                                              float* __restrict__ hnext) {
    __shared__ float As[64][17];
    __shared__ float Bs[64][17];
    int tid = threadIdx.x;
    int n0 = blockIdx.x * 64, m0 = blockIdx.y * 64;
    int rowL = tid >> 2, k4 = (tid & 3) * 4;
    int txm = tid & 15, txn = tid >> 4;
    float acc[4][4] = {};
    for (int k0 = 0; k0 < K1; k0 += 16) {
        const float* aptr;
        if (k0 < INQ)              aptr = x + ((long long)(m0 + rowL) * SQ + s) * INQ + k0;
        else if (k0 < INQ + WQ)    aptr = sc_rv + (m0 + rowL) * WQ + (k0 - INQ);
        else                       aptr = hprev + (m0 + rowL) * HQ + (k0 - INQ - WQ);
        float4 a = *(const float4*)(aptr + k4);
        float4 b = *(const float4*)(sc_Wcat + (long long)(n0 + rowL) * K1 + k0 + k4);
        As[rowL][k4 + 0] = a.x; As[rowL][k4 + 1] = a.y; As[rowL][k4 + 2] = a.z; As[rowL][k4 + 3] = a.w;
        Bs[rowL][k4 + 0] = b.x; Bs[rowL][k4 + 1] = b.y; Bs[rowL][k4 + 2] = b.z; Bs[rowL][k4 + 3] = b.w;
        __syncthreads();
        #pragma unroll
        for (int k = 0; k < 16; k++) {
            float av[4], bv[4];
            #pragma unroll
            for (int i = 0; i < 4; i++) av[i] = As[txm * 4 + i][k];
            #pragma unroll
            for (int j = 0; j < 4; j++) bv[j] = Bs[txn * 4 + j][k];
            #pragma unroll
            for (int i = 0; i < 4; i++)
                #pragma unroll
                for (int j = 0; j < 4; j++)
                    acc[i][j] = fmaf(av[i], bv[j], acc[i][j]);
        }
        __syncthreads();
    }
    // epilogue: each thread owns 4 batch rows x 1 full unit (4 gates)
    int u = (n0 >> 2) + txn;
    float bg0 = sc_bg[n0 + txn * 4 + 0], bg1 = sc_bg[n0 + txn * 4 + 1];
    float bg2 = sc_bg[n0 + txn * 4 + 2], bg3 = sc_bg[n0 + txn * 4 + 3];
    #pragma unroll
    for (int i = 0; i < 4; i++) {
        int b = m0 + txm * 4 + i;
        float i_ = acc[i][0] + bg0, f_ = acc[i][1] + bg1;
        float g_ = acc[i][2] + bg2, o_ = acc[i][3] + bg3;
        float c = sigmoidf_(f_) * sc_c[b * HQ + u] + sigmoidf_(i_) * tanhf(g_);
        sc_c[b * HQ + u] = c;
        hnext[b * HQ + u] = sigmoidf_(o_) * tanhf(c);
    }
}

// ---------------- 64x64 SGEMM (C = A @ B^T, padded dims, optional colscale) ----------------
__global__ __launch_bounds__(256) void sgemm64(
    const float* __restrict__ A, int lda,
    const float* __restrict__ B, int ldb,
    float* __restrict__ C, int ldc,
    const float* __restrict__ colscale, int K)
{
    __shared__ float As[64][17];
    __shared__ float Bs[64][17];
    int tid = threadIdx.x;
    int n0 = blockIdx.x * 64, m0 = blockIdx.y * 64;
    int rowL = tid >> 2, k4 = (tid & 3) * 4;
    int txm = tid & 15, txn = tid >> 4;
    float acc[4][4] = {};
    for (int k0 = 0; k0 < K; k0 += 16) {
        float4 a = *(const float4*)(A + (long long)(m0 + rowL) * lda + k0 + k4);
        float4 b = *(const float4*)(B + (long long)(n0 + rowL) * ldb + k0 + k4);
        As[rowL][k4 + 0] = a.x; As[rowL][k4 + 1] = a.y; As[rowL][k4 + 2] = a.z; As[rowL][k4 + 3] = a.w;
        Bs[rowL][k4 + 0] = b.x; Bs[rowL][k4 + 1] = b.y; Bs[rowL][k4 + 2] = b.z; Bs[rowL][k4 + 3] = b.w;
        __syncthreads();
        #pragma unroll
        for (int k = 0; k < 16; k++) {
            float av[4], bv[4];
            #pragma unroll
            for (int i = 0; i < 4; i++) av[i] = As[txm * 4 + i][k];
            #pragma unroll
            for (int j = 0; j < 4; j++) bv[j] = Bs[txn * 4 + j][k];
            #pragma unroll
            for (int i = 0; i < 4; i++)
                #pragma unroll
                for (int j = 0; j < 4; j++)
                    acc[i][j] = fmaf(av[i], bv[j], acc[i][j]);
        }
        __syncthreads();
    }
    float cs[4];
    #pragma unroll
    for (int j = 0; j < 4; j++) cs[j] = colscale ? colscale[n0 + txn * 4 + j] : 1.0f;
    #pragma unroll
    for (int i = 0; i < 4; i++) {
        int m = m0 + txm * 4 + i;
        #pragma unroll
        for (int j = 0; j < 4; j++)
            C[(long long)m * ldc + n0 + txn * 4 + j] = acc[i][j] * cs[j];
    }
}

// ---------------- 32x32 SGEMM for the small projection chain ----------------
__global__ __launch_bounds__(256) void sgemm32(
    const float* __restrict__ A, int lda,
    const float* __restrict__ B, int ldb,
    float* __restrict__ C, int ldc,
    const float* __restrict__ bias, int K)
{
    __shared__ float As[32][33];
    __shared__ float Bs[32][33];
    int tid = threadIdx.x;
    int n0 = blockIdx.x * 32, m0 = blockIdx.y * 32;
    int rowL = tid >> 3, k4 = (tid & 7) * 4;
    int tm = tid & 7, tn = tid >> 3;
    float acc[4] = {};
    for (int k0 = 0; k0 < K; k0 += 32) {
        float4 a = *(const float4*)(A + (long long)(m0 + rowL) * lda + k0 + k4);
        float4 b = *(const float4*)(B + (long long)(n0 + rowL) * ldb + k0 + k4);
        As[rowL][k4 + 0] = a.x; As[rowL][k4 + 1] = a.y; As[rowL][k4 + 2] = a.z; As[rowL][k4 + 3] = a.w;
        Bs[rowL][k4 + 0] = b.x; Bs[rowL][k4 + 1] = b.y; Bs[rowL][k4 + 2] = b.z; Bs[rowL][k4 + 3] = b.w;
        __syncthreads();
        #pragma unroll
        for (int k = 0; k < 32; k++) {
            float bv = Bs[tn][k];
            #pragma unroll
            for (int i = 0; i < 4; i++)
                acc[i] = fmaf(As[tm * 4 + i][k], bv, acc[i]);
        }
        __syncthreads();
    }
    float bb = bias ? bias[n0 + tn] : 0.0f;
    #pragma unroll
    for (int i = 0; i < 4; i++)
        C[(long long)(m0 + tm * 4 + i) * ldc + n0 + tn] = acc[i] + bb;
}

// ---------------- head processing ----------------
__device__ __forceinline__ float blockSum128(float v, float* sh) {
    #pragma unroll
    for (int o = 16; o; o >>= 1) v += __shfl_xor_sync(0xffffffffu, v, o);
    int wp = threadIdx.x >> 5;
    if ((threadIdx.x & 31) == 0) sh[wp] = v;
    __syncthreads();
    float r = sh[0] + sh[1] + sh[2] + sh[3];
    __syncthreads();
    return r;
}

__global__ __launch_bounds__(128) void k_headproc() {
    __shared__ float sh[4];
    int b = blockIdx.x, w = threadIdx.x;
    const float* hd = sc_heads + b * HRP;
    float rk = hd[w], wk = hd[130 + w];
    float nr2 = blockSum128(rk * rk, sh);
    float nw2 = blockSum128(wk * wk, sh);
    sc_keys[b * WQ + w]         = rk / fmaxf(sqrtf(nr2), 1e-12f);
    sc_keys[(128 + b) * WQ + w] = wk / fmaxf(sqrtf(nw2), 1e-12f);
    if (w == 0) {
        sc_beta[b]        = softplusf_(hd[128]);
        sc_gamma[b]       = 1.0f + softplusf_(hd[129]);
        sc_beta[128 + b]  = softplusf_(hd[258]);
        sc_gamma[128 + b] = 1.0f + softplusf_(hd[259]);
    }
    sc_er[b * WQ + w] = sigmoidf_(hd[260 + w]);
    sc_ad[b * WQ + w] = tanhf(hd[388 + w]);
}

__global__ void k_invnorm() {
    int row = blockIdx.x * (blockDim.x >> 5) + (threadIdx.x >> 5);
    int lane = threadIdx.x & 31;
    if (row >= NQ) return;
    const float* r = sc_mem + (long long)row * WQ;
    float s = 0.f;
    #pragma unroll
    for (int i = 0; i < 4; i++) { float v = r[lane + 32 * i]; s += v * v; }
    #pragma unroll
    for (int o = 16; o; o >>= 1) s += __shfl_xor_sync(0xffffffffu, s, o);
    if (lane == 0) sc_invn[row] = 1.0f / fmaxf(sqrtf(s), 1e-12f);
}

__global__ __launch_bounds__(256) void k_softmax() {
    __shared__ float sh[8];
    __shared__ float bc[2];
    int q = blockIdx.x, tid = threadIdx.x;
    float beta = sc_beta[q], gamma = sc_gamma[q];
    float* row = sc_sim + (long long)q * NQ;
    float mx = -1e30f;
    for (int n = tid; n < NQ; n += 256) mx = fmaxf(mx, row[n]);
    #pragma unroll
    for (int o = 16; o; o >>= 1) mx = fmaxf(mx, __shfl_xor_sync(0xffffffffu, mx, o));
    if ((tid & 31) == 0) sh[tid >> 5] = mx;
    __syncthreads();
    if (tid == 0) {
        float m = sh[0];
        #pragma unroll
        for (int i = 1; i < 8; i++) m = fmaxf(m, sh[i]);
        bc[0] = m;
    }
    __syncthreads();
    mx = bc[0];
    __syncthreads();
    float s = 0.f;
    for (int n = tid; n < NQ; n += 256) {
        float p = expf(beta * (row[n] - mx));
        row[n] = p;
        s += p;
    }
    #pragma unroll
    for (int o = 16; o; o >>= 1) s += __shfl_xor_sync(0xffffffffu, s, o);
    if ((tid & 31) == 0) sh[tid >> 5] = s;
    __syncthreads();
    if (tid == 0) {
        float t = 0.f;
        #pragma unroll
        for (int i = 0; i < 8; i++) t += sh[i];
        bc[1] = 1.0f / t;
    }
    __syncthreads();
    float inv = bc[1];
    if (q < 128) {
        float* rw = sc_rw + (long long)q * NQ;
        for (int n = tid; n < NQ; n += 256) {
            float wgt = row[n] * inv;
            rw[n] = gamma * wgt + (1.0f - gamma) * rw[n];
        }
    } else {
        float* ww = sc_ww + (long long)(q - 128) * NQ;
        float u = (1.0f - gamma) * (1.0f / (float)NQ);
        for (int n = tid; n < NQ; n += 256) {
            float wgt = row[n] * inv;
            ww[n] = gamma * wgt + u;
        }
    }
}

// mem[n,w] = mem[n,w]*(1 - sum_b ww[b,n]er[b,w]) + sum_b ww[b,n]ad[b,w]
__global__ __launch_bounds__(256) void k_memupdate() {
    __shared__ float sw[16][64], se[16][64], sa[16][64];
    int tid = threadIdx.x;
    int n0 = blockIdx.x * 64, w0 = blockIdx.y * 64;
    int txn = tid & 15, txw = tid >> 4;
    float ae[4][4] = {}, aa[4][4] = {};
    int kk = tid >> 4;
    int cb = (tid & 15) * 4;
    for (int b0 = 0; b0 < BQ; b0 += 16) {
        #pragma unroll
        for (int i = 0; i < 4; i++) {
            sw[kk][cb + i] = sc_ww[(long long)(b0 + kk) * NQ + n0 + cb + i];
            se[kk][cb + i] = sc_er[(b0 + kk) * WQ + w0 + cb + i];
            sa[kk][cb + i] = sc_ad[(b0 + kk) * WQ + w0 + cb + i];
        }
        __syncthreads();
        #pragma unroll
        for (int k = 0; k < 16; k++) {
            float wv[4], ev[4], av[4];
            #pragma unroll
            for (int i = 0; i < 4; i++) wv[i] = sw[k][txn * 4 + i];
            #pragma unroll
            for (int j = 0; j < 4; j++) { ev[j] = se[k][txw * 4 + j]; av[j] = sa[k][txw * 4 + j]; }
            #pragma unroll
            for (int i = 0; i < 4; i++)
                #pragma unroll
                for (int j = 0; j < 4; j++) {
                    ae[i][j] = fmaf(wv[i], ev[j], ae[i][j]);
                    aa[i][j] = fmaf(wv[i], av[j], aa[i][j]);
                }
        }
        __syncthreads();
    }
    #pragma unroll
    for (int i = 0; i < 4; i++) {
        int n = n0 + txn * 4 + i;
        #pragma unroll
        for (int j = 0; j < 4; j++) {
            int w = w0 + txw * 4 + j;
            long long idx = (long long)n * WQ + w;
            sc_mem[idx] = sc_mem[idx] * (1.0f - ae[i][j]) + aa[i][j];
        }
    }
}

// rv split-K
__global__ __launch_bounds__(256) void k_rvpart() {
    __shared__ float sr[16][128];
    __shared__ float sm[16][128];
    int tid = threadIdx.x;
    int kbase = blockIdx.x * 64;
    int txb = tid & 15, txw = tid >> 4;
    float acc[8][8] = {};
    for (int kk0 = 0; kk0 < 64; kk0 += 16) {
        #pragma unroll
        for (int i = 0; i < 8; i++) {
            int l = tid * 8 + i;
            int bb = l >> 4, k = l & 15;
            sr[k][bb] = sc_rw[(long long)bb * NQ + kbase + kk0 + k];
            int k2 = l >> 7, ww_ = l & 127;
            sm[k2][ww_] = sc_mem[(long long)(kbase + kk0 + k2) * WQ + ww_];
        }
        __syncthreads();
        #pragma unroll
        for (int k = 0; k < 16; k++) {
            float rb[8], mw[8];
            #pragma unroll
            for (int i = 0; i < 8; i++) rb[i] = sr[k][txb * 8 + i];
            #pragma unroll
            for (int j = 0; j < 8; j++) mw[j] = sm[k][txw * 8 + j];
            #pragma unroll
            for (int i = 0; i < 8; i++)
                #pragma unroll
                for (int j = 0; j < 8; j++)
                    acc[i][j] = fmaf(rb[i], mw[j], acc[i][j]);
        }
        __syncthreads();
    }
    float* dst = sc_rvpart + (long long)blockIdx.x * BQ * WQ;
    #pragma unroll
    for (int i = 0; i < 8; i++)
        #pragma unroll
        for (int j = 0; j < 8; j++)
            dst[(txb * 8 + i) * WQ + txw * 8 + j] = acc[i][j];
}

__global__ void k_rvreduce() {
    int idx = blockIdx.x * blockDim.x + threadIdx.x;
    if (idx >= BQ * WQ) return;
    float s = 0.f;
    for (int c = 0; c < NCHUNK; c++) s += sc_rvpart[(long long)c * BQ * WQ + idx];
    sc_rv[idx] = s;
}

// ---------------- host launcher ----------------
extern "C" void kernel_launch(void* const* d_in, const int* in_sizes, int n_in,
                              void* d_out, int out_size) {
    const float* x      = (const float*)d_in[0];
    const float* memory = (const float*)d_in[1];
    const float* Wih    = (const float*)d_in[2];
    const float* Whh    = (const float*)d_in[3];
    const float* bih    = (const float*)d_in[4];
    const float* bhh    = (const float*)d_in[5];
    const float* Wout   = (const float*)d_in[6];
    const float* bout   = (const float*)d_in[7];
    const float* rkW    = (const float*)d_in[8];
    const float* rkb    = (const float*)d_in[9];
    const float* rbW    = (const float*)d_in[10];
    const float* rbb    = (const float*)d_in[11];
    const float* rgW    = (const float*)d_in[12];
    const float* rgb    = (const float*)d_in[13];
    const float* wkW    = (const float*)d_in[14];
    const float* wkb    = (const float*)d_in[15];
    const float* wbW    = (const float*)d_in[16];
    const float* wbb    = (const float*)d_in[17];
    const float* wgW    = (const float*)d_in[18];
    const float* wgb    = (const float*)d_in[19];
    const float* erW    = (const float*)d_in[20];
    const float* erb    = (const float*)d_in[21];
    const float* adW    = (const float*)d_in[22];
    const float* adb    = (const float*)d_in[23];
    const float* pW     = (const float*)d_in[24];
    const float* pb     = (const float*)d_in[25];
    float* out          = (float*)d_out;

    float *phA, *phB, *pco, *pHW, *pHb, *pheads, *pkeys, *pmem, *psim, *pinvn, *pWoutP, *pboutP;
    cudaGetSymbolAddress((void**)&phA,    sc_hA);
    cudaGetSymbolAddress((void**)&phB,    sc_hB);
    cudaGetSymbolAddress((void**)&pco,    sc_co);
    cudaGetSymbolAddress((void**)&pHW,    sc_HW);
    cudaGetSymbolAddress((void**)&pHb,    sc_Hb);
    cudaGetSymbolAddress((void**)&pheads, sc_heads);
    cudaGetSymbolAddress((void**)&pkeys,  sc_keys);
    cudaGetSymbolAddress((void**)&pmem,   sc_mem);
    cudaGetSymbolAddress((void**)&psim,   sc_sim);
    cudaGetSymbolAddress((void**)&pinvn,  sc_invn);
    cudaGetSymbolAddress((void**)&pWoutP, sc_WoutP);
    cudaGetSymbolAddress((void**)&pboutP, sc_boutP);

    // prologue
    k_build_wcat<<<(int)(((long long)G4 * K1 + 255) / 256), 256>>>(Wih, Whh);
    k_build_bg<<<(G4 + 255) / 256, 256>>>(bih, bhh);
    k_build_woutp<<<(int)(((long long)CP * HQ + 255) / 256), 256>>>(Wout, bout);
    k_build_hw<<<(HRP * CP + 255) / 256, 256>>>(rkW, rbW, rgW, wkW, wbW, wgW, erW, adW,
                                                rkb, rbb, rgb, wkb, wbb, wgb, erb, adb);
    k_init<<<(int)(((long long)NQ * WQ + 511) / 512), 512>>>(memory);

    for (int s = 0; s < SQ; s++) {
        float* hprev = (s & 1) ? phB : phA;
        float* hnext = (s & 1) ? phA : phB;
        // 1. fused concat + LSTM gemm + gates -> hnext, c
        k_lstm<<<dim3(G4 / 64, BQ / 64), 256>>>(x, s, hprev, hnext);
        // 2. co = hnext @ WoutP^T + boutP   [128, 960] K=1024
        sgemm32<<<dim3(CP / 32, BQ / 32), 256>>>(hnext, HQ, pWoutP, HQ, pco, CP, pboutP, HQ);
        // 3. heads = co @ HW^T + Hb         [128, 576] K=960
        sgemm32<<<dim3(HRP / 32, BQ / 32), 256>>>(pco, CP, pHW, CP, pheads, HRP, pHb, CP);
        // 4. key norms, betas/gammas, erase/add
        k_headproc<<<BQ, 128>>>();
        // 5. memory row inverse norms
        k_invnorm<<<NQ / 8, 256>>>();
        // 6. sim = keys_norm @ mem^T * invn  [256, 16384] K=128
        sgemm64<<<dim3(NQ / 64, 256 / 64), 256>>>(pkeys, WQ, pmem, WQ, psim, NQ, pinvn, WQ);
        // 7. softmax + interpolation -> rw, ww
        k_softmax<<<2 * BQ, 256>>>();
        // 8. memory write
        k_memupdate<<<dim3(NQ / 64, WQ / 64), 256>>>();
        // 9. read rv = rw @ mem (split-K + deterministic reduce)
        k_rvpart<<<NCHUNK, 256>>>();
        k_rvreduce<<<(BQ * WQ + 255) / 256, 256>>>();
        // 10. out[:,s,:] = co[:, :512] @ pW^T + pb
        sgemm32<<<dim3(OUTQ / 32, BQ / 32), 256>>>(pco, CP, pW, OUTQ, out + (long long)s * OUTQ,
                                                   SQ * OUTQ, pb, OUTQ);
    }
}

// round 3
// speedup vs baseline: 1.8394x; 1.2200x over previous
#include <cuda_runtime.h>
#include <math.h>

// ---------------- problem dims ----------------
#define BQ   128
#define SQ   32
#define INQ  512
#define HQ   1024
#define OUTQ 512
#define NQ   16384
#define WQ   128
#define CQ   899
#define CP   960
#define K1   1664         // IN + W + H
#define KR   1152         // W + H (recurrent part)
#define G4   4096
#define HRP  576
#define NCHUNK 256
#define MQ   4096         // S*B rows for xg precompute

// ---------------- device scratch ----------------
__device__ float sc_mem[NQ * WQ];
__device__ float sc_Wcat[G4 * K1];          // gate-interleaved [Wih | Whh]
__device__ float sc_bg[G4];
__device__ float sc_WoutP[CP * HQ];         // padded Wout
__device__ float sc_HW[HRP * CP];           // packed padded head weights
__device__ float sc_Hb[HRP];
__device__ float sc_HWc[HRP * HQ];          // folded HW @ Wout
__device__ float sc_Hbc[HRP];
__device__ float sc_pWc[OUTQ * HQ];         // folded pW @ Wout[:512]
__device__ float sc_pbc[OUTQ];
__device__ float sc_xg[(long long)MQ * G4]; // precomputed x-projection
__device__ float sc_hA[BQ * HQ];
__device__ float sc_hB[BQ * HQ];
__device__ float sc_c[BQ * HQ];
__device__ float sc_rv[BQ * WQ];
__device__ float sc_rw[BQ * NQ];
__device__ float sc_ww[BQ * NQ];
__device__ float sc_heads[BQ * HRP];
__device__ float sc_keys[2 * BQ * WQ];
__device__ float sc_beta[2 * BQ];
__device__ float sc_gamma[2 * BQ];
__device__ float sc_er[BQ * WQ];
__device__ float sc_ad[BQ * WQ];
__device__ float sc_sim[2 * BQ * NQ];
__device__ float sc_invn[NQ];
__device__ float sc_rvpart[NCHUNK * BQ * WQ];

// ---------------- helpers ----------------
__device__ __forceinline__ float sigmoidf_(float x) { return 1.0f / (1.0f + expf(-x)); }
__device__ __forceinline__ float softplusf_(float x) { return x > 20.0f ? x : log1pf(expf(x)); }

__device__ __forceinline__ float blockSum128(float v, float* sh) {
    #pragma unroll
    for (int o = 16; o; o >>= 1) v += __shfl_xor_sync(0xffffffffu, v, o);
    int wp = threadIdx.x >> 5;
    if ((threadIdx.x & 31) == 0) sh[wp] = v;
    __syncthreads();
    float r = sh[0] + sh[1] + sh[2] + sh[3];
    __syncthreads();
    return r;
}

// ---------------- prologue kernels ----------------
__global__ void k_build_wcat(const float* __restrict__ Wih, const float* __restrict__ Whh) {
    long long idx = (long long)blockIdx.x * blockDim.x + threadIdx.x;
    if (idx >= (long long)G4 * K1) return;
    int r = (int)(idx / K1), k = (int)(idx % K1);
    int j = r >> 2, g = r & 3;
    int src = g * HQ + j;
    sc_Wcat[idx] = (k < INQ + WQ) ? Wih[src * (INQ + WQ) + k] : Whh[src * HQ + (k - INQ - WQ)];
}

__global__ void k_build_bg(const float* __restrict__ bih, const float* __restrict__ bhh) {
    int r = blockIdx.x * blockDim.x + threadIdx.x;
    if (r >= G4) return;
    int j = r >> 2, g = r & 3;
    int src = g * HQ + j;
    sc_bg[r] = bih[src] + bhh[src];
}

__global__ void k_build_woutp(const float* __restrict__ Wout) {
    long long idx = (long long)blockIdx.x * blockDim.x + threadIdx.x;
    if (idx >= (long long)CP * HQ) return;
    int r = (int)(idx / HQ), k = (int)(idx % HQ);
    sc_WoutP[idx] = (r < CQ) ? Wout[(long long)r * HQ + k] : 0.0f;
}

__global__ void k_build_hw(const float* rkW, const float* rbW, const float* rgW,
                           const float* wkW, const float* wbW, const float* wgW,
                           const float* erW, const float* adW,
                           const float* rkb, const float* rbb, const float* rgb,
                           const float* wkb, const float* wbb, const float* wgb,
                           const float* erb, const float* adb) {
    int idx = blockIdx.x * blockDim.x + threadIdx.x;
    if (idx >= HRP * CP) return;
    int r = idx / CP, k = idx % CP;
    float wv = 0.0f, bv = 0.0f;
    if (k < CQ && r < 516) {
        if (r < 128)      { wv = rkW[r * CQ + k];         bv = rkb[r]; }
        else if (r == 128){ wv = rbW[k];                  bv = rbb[0]; }
        else if (r == 129){ wv = rgW[k];                  bv = rgb[0]; }
        else if (r < 258) { wv = wkW[(r - 130) * CQ + k]; bv = wkb[r - 130]; }
        else if (r == 258){ wv = wbW[k];                  bv = wbb[0]; }
        else if (r == 259){ wv = wgW[k];                  bv = wgb[0]; }
        else if (r < 388) { wv = erW[(r - 260) * CQ + k]; bv = erb[r - 260]; }
        else              { wv = adW[(r - 388) * CQ + k]; bv = adb[r - 388]; }
    }
    sc_HW[idx] = wv;
    if (k == 0) sc_Hb[r] = bv;
}

__global__ void k_init(const float* __restrict__ memory) {
    long long i = (long long)blockIdx.x * blockDim.x + threadIdx.x;
    long long tot = (long long)NQ * WQ;
    if (i < tot) {
        sc_mem[i] = memory[i];
        sc_rw[i]  = 1.0f / (float)NQ;
    }
    if (i < BQ * HQ) { sc_hA[i] = 0.0f; sc_hB[i] = 0.0f; sc_c[i] = 0.0f; }
    if (i < BQ * WQ) sc_rv[i] = 0.0f;
}

__global__ void k_invnorm() {
    int row = blockIdx.x * (blockDim.x >> 5) + (threadIdx.x >> 5);
    int lane = threadIdx.x & 31;
    if (row >= NQ) return;
    const float* r = sc_mem + (long long)row * WQ;
    float s = 0.f;
    #pragma unroll
    for (int i = 0; i < 4; i++) { float v = r[lane + 32 * i]; s += v * v; }
    #pragma unroll
    for (int o = 16; o; o >>= 1) s += __shfl_xor_sync(0xffffffffu, s, o);
    if (lane == 0) sc_invn[row] = 1.0f / fmaxf(sqrtf(s), 1e-12f);
}

// biases fold: Hbc = HW @ bout + Hb ; pbc = pW @ bout[:512] + pb
__global__ __launch_bounds__(128) void k_biases(const float* __restrict__ bout,
                                                const float* __restrict__ pW,
                                                const float* __restrict__ pb) {
    __shared__ float sh[4];
    int r = blockIdx.x, t = threadIdx.x;
    float s = 0.f;
    if (r < HRP) {
        for (int c = t; c < CQ; c += 128) s += sc_HW[r * CP + c] * bout[c];
        s = blockSum128(s, sh);
        if (t == 0) sc_Hbc[r] = s + sc_Hb[r];
    } else {
        int o = r - HRP;
        for (int c = t; c < OUTQ; c += 128) s += pW[o * OUTQ + c] * bout[c];
        s = blockSum128(s, sh);
        if (t == 0) sc_pbc[o] = s + pb[o];
    }
}

// C[M,N] = A[M,K] @ B[K,N]  (non-transposed B, 32x32 tiles)
__global__ __launch_bounds__(256) void sgemm_nn32(
    const float* __restrict__ A, int lda,
    const float* __restrict__ B, int ldb,
    float* __restrict__ C, int ldc, int K)
{
    __shared__ float As[32][36];
    __shared__ float Bs[32][36];
    int tid = threadIdx.x;
    int n0 = blockIdx.x * 32, m0 = blockIdx.y * 32;
    int rowL = tid >> 3, k4 = (tid & 7) * 4;
    int tm = tid & 7, tn = tid >> 3;
    float acc[4] = {};
    for (int k0 = 0; k0 < K; k0 += 32) {
        float4 a = *(const float4*)(A + (long long)(m0 + rowL) * lda + k0 + k4);
        As[rowL][k4 + 0] = a.x; As[rowL][k4 + 1] = a.y; As[rowL][k4 + 2] = a.z; As[rowL][k4 + 3] = a.w;
        float4 b = *(const float4*)(B + (long long)(k0 + rowL) * ldb + n0 + k4);
        Bs[rowL][k4 + 0] = b.x; Bs[rowL][k4 + 1] = b.y; Bs[rowL][k4 + 2] = b.z; Bs[rowL][k4 + 3] = b.w;
        __syncthreads();
        #pragma unroll
        for (int k = 0; k < 32; k++) {
            float bv = Bs[k][tn];
            #pragma unroll
            for (int i = 0; i < 4; i++)
                acc[i] = fmaf(As[tm * 4 + i][k], bv, acc[i]);
        }
        __syncthreads();
    }
    #pragma unroll
    for (int i = 0; i < 4; i++)
        C[(long long)(m0 + tm * 4 + i) * ldc + n0 + tn] = acc[i];
}

// xg[s*B+b, n] = x[b,s,:] @ Wcat[n, :512]^T  (64x64 tile, As[k][m] layout)
__global__ __launch_bounds__(256) void k_xg(const float* __restrict__ x) {
    __shared__ float As[16][68];
    __shared__ float Bs[16][68];
    int tid = threadIdx.x;
    int n0 = blockIdx.x * 64, m0 = blockIdx.y * 64;
    int rowL = tid >> 2, k4 = (tid & 3) * 4;
    int txm = tid & 15, txn = tid >> 4;
    float acc[4][4] = {};
    int m = m0 + rowL;
    int s_ = m >> 7, b_ = m & 127;
    const float* arow = x + ((long long)b_ * SQ + s_) * INQ;
    const float* brow = sc_Wcat + (long long)(n0 + rowL) * K1;
    for (int k0 = 0; k0 < INQ; k0 += 16) {
        float4 a = *(const float4*)(arow + k0 + k4);
        float4 b = *(const float4*)(brow + k0 + k4);
        As[k4 + 0][rowL] = a.x; As[k4 + 1][rowL] = a.y; As[k4 + 2][rowL] = a.z; As[k4 + 3][rowL] = a.w;
        Bs[k4 + 0][rowL] = b.x; Bs[k4 + 1][rowL] = b.y; Bs[k4 + 2][rowL] = b.z; Bs[k4 + 3][rowL] = b.w;
        __syncthreads();
        #pragma unroll
        for (int k = 0; k < 16; k++) {
            float4 av = *(const float4*)&As[k][txm * 4];
            float4 bv = *(const float4*)&Bs[k][txn * 4];
            float aa[4] = {av.x, av.y, av.z, av.w};
            float bb[4] = {bv.x, bv.y, bv.z, bv.w};
            #pragma unroll
            for (int i = 0; i < 4; i++)
                #pragma unroll
                for (int j = 0; j < 4; j++)
                    acc[i][j] = fmaf(aa[i], bb[j], acc[i][j]);
        }
        __syncthreads();
    }
    #pragma unroll
    for (int i = 0; i < 4; i++) {
        long long mi = m0 + txm * 4 + i;
        #pragma unroll
        for (int j = 0; j < 4; j++)
            sc_xg[mi * G4 + n0 + txn * 4 + j] = acc[i][j];
    }
}

// ---------------- per-step kernels ----------------
// fused LSTM: recurrent GEMM (K=1152) + precomputed xg + gates
__global__ __launch_bounds__(256) void k_lstm(int s, const float* __restrict__ hprev,
                                              float* __restrict__ hnext) {
    __shared__ float As[16][68];
    __shared__ float Bs[16][68];
    int tid = threadIdx.x;
    int n0 = blockIdx.x * 64, m0 = blockIdx.y * 64;
    int rowL = tid >> 2, k4 = (tid & 3) * 4;
    int txm = tid & 15, txn = tid >> 4;
    float acc[4][4] = {};
    const float* brow = sc_Wcat + (long long)(n0 + rowL) * K1 + INQ;
    for (int k0 = 0; k0 < KR; k0 += 16) {
        int kg = k0 + k4;
        const float* ap = (kg < WQ) ? (sc_rv + (m0 + rowL) * WQ + kg)
                                    : (hprev + (m0 + rowL) * HQ + (kg - WQ));
        float4 a = *(const float4*)ap;
        float4 b = *(const float4*)(brow + k0 + k4);
        As[k4 + 0][rowL] = a.x; As[k4 + 1][rowL] = a.y; As[k4 + 2][rowL] = a.z; As[k4 + 3][rowL] = a.w;
        Bs[k4 + 0][rowL] = b.x; Bs[k4 + 1][rowL] = b.y; Bs[k4 + 2][rowL] = b.z; Bs[k4 + 3][rowL] = b.w;
        __syncthreads();
        #pragma unroll
        for (int k = 0; k < 16; k++) {
            float4 av = *(const float4*)&As[k][txm * 4];
            float4 bv = *(const float4*)&Bs[k][txn * 4];
            float aa[4] = {av.x, av.y, av.z, av.w};
            float bb[4] = {bv.x, bv.y, bv.z, bv.w};
            #pragma unroll
            for (int i = 0; i < 4; i++)
                #pragma unroll
                for (int j = 0; j < 4; j++)
                    acc[i][j] = fmaf(aa[i], bb[j], acc[i][j]);
        }
        __syncthreads();
    }
    int u = (n0 >> 2) + txn;
    float4 bg4 = *(const float4*)&sc_bg[n0 + txn * 4];
    #pragma unroll
    for (int i = 0; i < 4; i++) {
        int b = m0 + txm * 4 + i;
        float4 xg4 = *(const float4*)&sc_xg[((long long)s * BQ + b) * G4 + n0 + txn * 4];
        float i_ = acc[i][0] + xg4.x + bg4.x;
        float f_ = acc[i][1] + xg4.y + bg4.y;
        float g_ = acc[i][2] + xg4.z + bg4.z;
        float o_ = acc[i][3] + xg4.w + bg4.w;
        float c = sigmoidf_(f_) * sc_c[b * HQ + u] + sigmoidf_(i_) * tanhf(g_);
        sc_c[b * HQ + u] = c;
        hnext[b * HQ + u] = sigmoidf_(o_) * tanhf(c);
    }
}

// 32x32 SGEMM: C = A @ B^T + bias
__global__ __launch_bounds__(256) void sgemm32(
    const float* __restrict__ A, int lda,
    const float* __restrict__ B, int ldb,
    float* __restrict__ C, int ldc,
    const float* __restrict__ bias, int K)
{
    __shared__ float As[32][33];
    __shared__ float Bs[32][33];
    int tid = threadIdx.x;
    int n0 = blockIdx.x * 32, m0 = blockIdx.y * 32;
    int rowL = tid >> 3, k4 = (tid & 7) * 4;
    int tm = tid & 7, tn = tid >> 3;
    float acc[4] = {};
    for (int k0 = 0; k0 < K; k0 += 32) {
        float4 a = *(const float4*)(A + (long long)(m0 + rowL) * lda + k0 + k4);
        float4 b = *(const float4*)(B + (long long)(n0 + rowL) * ldb + k0 + k4);
        As[rowL][k4 + 0] = a.x; As[rowL][k4 + 1] = a.y; As[rowL][k4 + 2] = a.z; As[rowL][k4 + 3] = a.w;
        Bs[rowL][k4 + 0] = b.x; Bs[rowL][k4 + 1] = b.y; Bs[rowL][k4 + 2] = b.z; Bs[rowL][k4 + 3] = b.w;
        __syncthreads();
        #pragma unroll
        for (int k = 0; k < 32; k++) {
            float bv = Bs[tn][k];
            #pragma unroll
            for (int i = 0; i < 4; i++)
                acc[i] = fmaf(As[tm * 4 + i][k], bv, acc[i]);
        }
        __syncthreads();
    }
    float bb = bias ? bias[n0 + tn] : 0.0f;
    #pragma unroll
    for (int i = 0; i < 4; i++)
        C[(long long)(m0 + tm * 4 + i) * ldc + n0 + tn] = acc[i] + bb;
}

__global__ __launch_bounds__(128) void k_headproc() {
    __shared__ float sh[4];
    int b = blockIdx.x, w = threadIdx.x;
    const float* hd = sc_heads + b * HRP;
    float rk = hd[w], wk = hd[130 + w];
    float nr2 = blockSum128(rk * rk, sh);
    float nw2 = blockSum128(wk * wk, sh);
    sc_keys[b * WQ + w]         = rk / fmaxf(sqrtf(nr2), 1e-12f);
    sc_keys[(128 + b) * WQ + w] = wk / fmaxf(sqrtf(nw2), 1e-12f);
    if (w == 0) {
        sc_beta[b]        = softplusf_(hd[128]);
        sc_gamma[b]       = 1.0f + softplusf_(hd[129]);
        sc_beta[128 + b]  = softplusf_(hd[258]);
        sc_gamma[128 + b] = 1.0f + softplusf_(hd[259]);
    }
    sc_er[b * WQ + w] = sigmoidf_(hd[260 + w]);
    sc_ad[b * WQ + w] = tanhf(hd[388 + w]);
}

// sim = keys @ mem^T, col-scaled by invn (64x64 tile)
__global__ __launch_bounds__(256) void k_sim() {
    __shared__ float As[16][68];
    __shared__ float Bs[16][68];
    int tid = threadIdx.x;
    int n0 = blockIdx.x * 64, m0 = blockIdx.y * 64;
    int rowL = tid >> 2, k4 = (tid & 3) * 4;
    int txm = tid & 15, txn = tid >> 4;
    float acc[4][4] = {};
    const float* arow = sc_keys + (long long)(m0 + rowL) * WQ;
    const float* brow = sc_mem + (long long)(n0 + rowL) * WQ;
    for (int k0 = 0; k0 < WQ; k0 += 16) {
        float4 a = *(const float4*)(arow + k0 + k4);
        float4 b = *(const float4*)(brow + k0 + k4);
        As[k4 + 0][rowL] = a.x; As[k4 + 1][rowL] = a.y; As[k4 + 2][rowL] = a.z; As[k4 + 3][rowL] = a.w;
        Bs[k4 + 0][rowL] = b.x; Bs[k4 + 1][rowL] = b.y; Bs[k4 + 2][rowL] = b.z; Bs[k4 + 3][rowL] = b.w;
        __syncthreads();
        #pragma unroll
        for (int k = 0; k < 16; k++) {
            float4 av = *(const float4*)&As[k][txm * 4];
            float4 bv = *(const float4*)&Bs[k][txn * 4];
            float aa[4] = {av.x, av.y, av.z, av.w};
            float bb[4] = {bv.x, bv.y, bv.z, bv.w};
            #pragma unroll
            for (int i = 0; i < 4; i++)
                #pragma unroll
                for (int j = 0; j < 4; j++)
                    acc[i][j] = fmaf(aa[i], bb[j], acc[i][j]);
        }
        __syncthreads();
    }
    float4 cs = *(const float4*)&sc_invn[n0 + txn * 4];
    float csv[4] = {cs.x, cs.y, cs.z, cs.w};
    #pragma unroll
    for (int i = 0; i < 4; i++) {
        long long m = m0 + txm * 4 + i;
        #pragma unroll
        for (int j = 0; j < 4; j++)
            sc_sim[m * NQ + n0 + txn * 4 + j] = acc[i][j] * csv[j];
    }
}

// register-resident softmax + interpolation (one read of sim, one write of rw/ww)
__global__ __launch_bounds__(512) void k_softmax512() {
    __shared__ float sh[16];
    __shared__ float bcv;
    int q = blockIdx.x, tid = threadIdx.x;
    int lane = tid & 31, wid = tid >> 5;
    float beta = sc_beta[q], gamma = sc_gamma[q];
    const float* row = sc_sim + (long long)q * NQ;
    float v[32];
    float mx = -1e30f;
    #pragma unroll
    for (int i = 0; i < 32; i++) { v[i] = row[tid + i * 512]; mx = fmaxf(mx, v[i]); }
    #pragma unroll
    for (int o = 16; o; o >>= 1) mx = fmaxf(mx, __shfl_xor_sync(0xffffffffu, mx, o));
    if (lane == 0) sh[wid] = mx;
    __syncthreads();
    if (tid == 0) {
        float m = sh[0];
        #pragma unroll
        for (int i = 1; i < 16; i++) m = fmaxf(m, sh[i]);
        bcv = m;
    }
    __syncthreads();
    mx = bcv;
    float s = 0.f;
    #pragma unroll
    for (int i = 0; i < 32; i++) { v[i] = expf(beta * (v[i] - mx)); s += v[i]; }
    __syncthreads();   // protect sh/bcv reuse
    #pragma unroll
    for (int o = 16; o; o >>= 1) s += __shfl_xor_sync(0xffffffffu, s, o);
    if (lane == 0) sh[wid] = s;
    __syncthreads();
    if (tid == 0) {
        float t = 0.f;
        #pragma unroll
        for (int i = 0; i < 16; i++) t += sh[i];
        bcv = 1.0f / t;
    }
    __syncthreads();
    float inv = bcv;
    if (q < 128) {
        float* rw = sc_rw + (long long)q * NQ;
        #pragma unroll
        for (int i = 0; i < 32; i++) {
            int n = tid + i * 512;
            rw[n] = gamma * (v[i] * inv) + (1.0f - gamma) * rw[n];
        }
    } else {
        float* ww = sc_ww + (long long)(q - 128) * NQ;
        float u = (1.0f - gamma) * (1.0f / (float)NQ);
        #pragma unroll
        for (int i = 0; i < 32; i++)
            ww[tid + i * 512] = gamma * (v[i] * inv) + u;
    }
}

// fused: memory erase/add update + next-step invnorm + rv split-K partials
__global__ __launch_bounds__(256) void k_memupd_rv() {
    __shared__ __align__(16) float mns[64][132];
    __shared__ __align__(16) float ubuf[2656];   // phase A: sw/se/sa ; phase B: srw
    __shared__ float rowsq[64][4];
    float (*sw)[68]   = (float(*)[68])ubuf;
    float (*se)[132]  = (float(*)[132])(ubuf + 8 * 68);
    float (*sa)[132]  = (float(*)[132])(ubuf + 8 * 68 + 8 * 132);
    float (*srw)[132] = (float(*)[132])ubuf;
    int tid = threadIdx.x;
    int n0 = blockIdx.x * 64;
    int txn = tid & 15, txw = tid >> 4;
    float ae[4][8] = {}, aa[4][8] = {};
    for (int b0 = 0; b0 < BQ; b0 += 8) {
        {
            int kk = tid >> 5, half = tid & 31;
            *(float2*)&sw[kk][half * 2] = *(const float2*)&sc_ww[(long long)(b0 + kk) * NQ + n0 + half * 2];
            *(float4*)&se[kk][half * 4] = *(const float4*)&sc_er[(b0 + kk) * WQ + half * 4];
            *(float4*)&sa[kk][half * 4] = *(const float4*)&sc_ad[(b0 + kk) * WQ + half * 4];
        }
        __syncthreads();
        #pragma unroll
        for (int k = 0; k < 8; k++) {
            float4 w4 = *(const float4*)&sw[k][txn * 4];
            float4 e0 = *(const float4*)&se[k][txw * 8];
            float4 e1 = *(const float4*)&se[k][txw * 8 + 4];
            float4 a0 = *(const float4*)&sa[k][txw * 8];
            float4 a1 = *(const float4*)&sa[k][txw * 8 + 4];
            float wv[4] = {w4.x, w4.y, w4.z, w4.w};
            float ev[8] = {e0.x, e0.y, e0.z, e0.w, e1.x, e1.y, e1.z, e1.w};
            float av[8] = {a0.x, a0.y, a0.z, a0.w, a1.x, a1.y, a1.z, a1.w};
            #pragma unroll
            for (int i = 0; i < 4; i++)
                #pragma unroll
                for (int j = 0; j < 8; j++) {
                    ae[i][j] = fmaf(wv[i], ev[j], ae[i][j]);
                    aa[i][j] = fmaf(wv[i], av[j], aa[i][j]);
                }
        }
        __syncthreads();
    }
    // epilogue A: mem update, stage new tile in smem
    #pragma unroll
    for (int i = 0; i < 4; i++) {
        int nl = txn * 4 + i;
        long long base = (long long)(n0 + nl) * WQ + txw * 8;
        float4 m0v = *(const float4*)&sc_mem[base];
        float4 m1v = *(const float4*)&sc_mem[base + 4];
        float r[8] = {m0v.x, m0v.y, m0v.z, m0v.w, m1v.x, m1v.y, m1v.z, m1v.w};
        #pragma unroll
        for (int j = 0; j < 8; j++) r[j] = r[j] * (1.0f - ae[i][j]) + aa[i][j];
        *(float4*)&sc_mem[base]     = make_float4(r[0], r[1], r[2], r[3]);
        *(float4*)&sc_mem[base + 4] = make_float4(r[4], r[5], r[6], r[7]);
        *(float4*)&mns[nl][txw * 8]     = make_float4(r[0], r[1], r[2], r[3]);
        *(float4*)&mns[nl][txw * 8 + 4] = make_float4(r[4], r[5], r[6], r[7]);
    }
    __syncthreads();
    // invnorm of new rows (next step's sim normalization)
    {
        int r = tid >> 2, qq = tid & 3;
        float s = 0.f;
        #pragma unroll
        for (int t = 0; t < 32; t += 4) {
            float4 v = *(const float4*)&mns[r][qq * 32 + t];
            s += v.x * v.x + v.y * v.y + v.z * v.z + v.w * v.w;
        }
        rowsq[r][qq] = s;
    }
    __syncthreads();
    if (tid < 64) {
        float s = rowsq[tid][0] + rowsq[tid][1] + rowsq[tid][2] + rowsq[tid][3];
        sc_invn[n0 + tid] = 1.0f / fmaxf(sqrtf(s), 1e-12f);
    }
    // phase B: rv partials = rw[:, tile] @ mns
    int tb = tid & 15, tw = tid >> 4;
    float racc[8][8] = {};
    for (int nc = 0; nc < 4; nc++) {
        __syncthreads();
        #pragma unroll
        for (int r = 0; r < 8; r++) {
            int b = (tid >> 4) + r * 16, nn = tid & 15;
            srw[nn][b] = sc_rw[(long long)b * NQ + n0 + nc * 16 + nn];
        }
        __syncthreads();
        #pragma unroll
        for (int nn = 0; nn < 16; nn++) {
            float4 r0 = *(const float4*)&srw[nn][tb * 8];
            float4 r1 = *(const float4*)&srw[nn][tb * 8 + 4];
            int nl = nc * 16 + nn;
            float4 q0 = *(const float4*)&mns[nl][tw * 8];
            float4 q1 = *(const float4*)&mns[nl][tw * 8 + 4];
            float rb[8] = {r0.x, r0.y, r0.z, r0.w, r1.x, r1.y, r1.z, r1.w};
            float mw[8] = {q0.x, q0.y, q0.z, q0.w, q1.x, q1.y, q1.z, q1.w};
            #pragma unroll
            for (int i = 0; i < 8; i++)
                #pragma unroll
                for (int j = 0; j < 8; j++)
                    racc[i][j] = fmaf(rb[i], mw[j], racc[i][j]);
        }
    }
    float* dst = sc_rvpart + (long long)blockIdx.x * BQ * WQ;
    #pragma unroll
    for (int i = 0; i < 8; i++) {
        int b = tb * 8 + i;
        *(float4*)&dst[b * WQ + tw * 8]     = make_float4(racc[i][0], racc[i][1], racc[i][2], racc[i][3]);
        *(float4*)&dst[b * WQ + tw * 8 + 4] = make_float4(racc[i][4], racc[i][5], racc[i][6], racc[i][7]);
    }
}

__global__ void k_rvreduce() {
    int idx = blockIdx.x * blockDim.x + threadIdx.x;   // float4 units, 4096 total
    const float4* p = (const float4*)sc_rvpart;
    float4 s = make_float4(0.f, 0.f, 0.f, 0.f);
    #pragma unroll 8
    for (int c = 0; c < NCHUNK; c++) {
        float4 t = p[(long long)c * 4096 + idx];
        s.x += t.x; s.y += t.y; s.z += t.z; s.w += t.w;
    }
    ((float4*)sc_rv)[idx] = s;
}

// ---------------- host launcher ----------------
extern "C" void kernel_launch(void* const* d_in, const int* in_sizes, int n_in,
                              void* d_out, int out_size) {
    const float* x      = (const float*)d_in[0];
    const float* memory = (const float*)d_in[1];
    const float* Wih    = (const float*)d_in[2];
    const float* Whh    = (const float*)d_in[3];
    const float* bih    = (const float*)d_in[4];
    const float* bhh    = (const float*)d_in[5];
    const float* Wout   = (const float*)d_in[6];
    const float* bout   = (const float*)d_in[7];
    const float* rkW    = (const float*)d_in[8];
    const float* rkb    = (const float*)d_in[9];
    const float* rbW    = (const float*)d_in[10];
    const float* rbb    = (const float*)d_in[11];
    const float* rgW    = (const float*)d_in[12];
    const float* rgb    = (const float*)d_in[13];
    const float* wkW    = (const float*)d_in[14];
    const float* wkb    = (const float*)d_in[15];
    const float* wbW    = (const float*)d_in[16];
    const float* wbb    = (const float*)d_in[17];
    const float* wgW    = (const float*)d_in[18];
    const float* wgb    = (const float*)d_in[19];
    const float* erW    = (const float*)d_in[20];
    const float* erb    = (const float*)d_in[21];
    const float* adW    = (const float*)d_in[22];
    const float* adb    = (const float*)d_in[23];
    const float* pW     = (const float*)d_in[24];
    const float* pb     = (const float*)d_in[25];
    float* out          = (float*)d_out;

    float *phA, *phB, *pHW, *pHWc, *pHbc, *pWoutP, *ppWc, *ppbc, *pheads;
    cudaGetSymbolAddress((void**)&phA,    sc_hA);
    cudaGetSymbolAddress((void**)&phB,    sc_hB);
    cudaGetSymbolAddress((void**)&pHW,    sc_HW);
    cudaGetSymbolAddress((void**)&pHWc,   sc_HWc);
    cudaGetSymbolAddress((void**)&pHbc,   sc_Hbc);
    cudaGetSymbolAddress((void**)&pWoutP, sc_WoutP);
    cudaGetSymbolAddress((void**)&ppWc,   sc_pWc);
    cudaGetSymbolAddress((void**)&ppbc,   sc_pbc);
    cudaGetSymbolAddress((void**)&pheads, sc_heads);

    // ---- prologue ----
    k_build_wcat<<<(int)(((long long)G4 * K1 + 255) / 256), 256>>>(Wih, Whh);
    k_build_bg<<<(G4 + 255) / 256, 256>>>(bih, bhh);
    k_build_woutp<<<(int)(((long long)CP * HQ + 255) / 256), 256>>>(Wout);
    k_build_hw<<<(HRP * CP + 255) / 256, 256>>>(rkW, rbW, rgW, wkW, wbW, wgW, erW, adW,
                                                rkb, rbb, rgb, wkb, wbb, wgb, erb, adb);
    k_init<<<(int)(((long long)NQ * WQ + 511) / 512), 512>>>(memory);
    k_invnorm<<<NQ / 8, 256>>>();
    k_xg<<<dim3(G4 / 64, MQ / 64), 256>>>(x);
    // HWc = HW @ WoutP   [576,1024] K=960
    sgemm_nn32<<<dim3(HQ / 32, HRP / 32), 256>>>(pHW, CP, pWoutP, HQ, pHWc, HQ, CP);
    // pWc = pW @ Wout[:512]  [512,1024] K=512
    sgemm_nn32<<<dim3(HQ / 32, OUTQ / 32), 256>>>(pW, OUTQ, Wout, HQ, ppWc, HQ, OUTQ);
    k_biases<<<HRP + OUTQ, 128>>>(bout, pW, pb);

    // ---- timestep loop ----
    for (int s = 0; s < SQ; s++) {
        float* hprev = (s & 1) ? phB : phA;
        float* hnext = (s & 1) ? phA : phB;
        k_lstm<<<dim3(G4 / 64, BQ / 64), 256>>>(s, hprev, hnext);
        // heads = h @ HWc^T + Hbc   [128,576] K=1024
        sgemm32<<<dim3(HRP / 32, BQ / 32), 256>>>(hnext, HQ, pHWc, HQ, pheads, HRP, pHbc, HQ);
        k_headproc<<<BQ, 128>>>();
        k_sim<<<dim3(NQ / 64, 2 * BQ / 64), 256>>>();
        k_softmax512<<<2 * BQ, 512>>>();
        k_memupd_rv<<<NQ / 64, 256>>>();
        k_rvreduce<<<16, 256>>>();
        // out[:,s,:] = h @ pWc^T + pbc
        sgemm32<<<dim3(OUTQ / 32, BQ / 32), 256>>>(hnext, HQ, ppWc, HQ, out + (long long)s * OUTQ,
                                                   SQ * OUTQ, ppbc, HQ);
    }
}

// round 4
// speedup vs baseline: 2.5657x; 1.3949x over previous
#include <cuda_runtime.h>
#include <math.h>

// ---------------- problem dims ----------------
#define BQ   128
#define SQ   32
#define INQ  512
#define HQ   1024
#define OUTQ 512
#define NQ   16384
#define WQ   128
#define CQ   899
#define CP   960
#define K1   1664         // IN + W + H
#define KR   1152         // W + H (recurrent)
#define KSL  384          // K-slice for split-K LSTM
#define G4   4096
#define HRP  576
#define HOW  1088         // merged heads(576) + out(512) rows
#define NCHUNK 256
#define MQ   4096

// ---------------- device scratch ----------------
__device__ float sc_mem[NQ * WQ];
__device__ float sc_Wcat[G4 * K1];
__device__ float sc_bg[G4];
__device__ float sc_WoutP[CP * HQ];
__device__ float sc_HW[HRP * CP];
__device__ float sc_Hb[HRP];
__device__ float sc_HOW[HOW * HQ];          // rows 0..575: HW@Wout ; 576..1087: pW@Wout[:512]
__device__ float sc_HOb[HOW];
__device__ float sc_xg[(long long)MQ * G4];
__device__ float sc_g3[3 * BQ * G4];        // split-K LSTM partials
__device__ float sc_hA[BQ * HQ];
__device__ float sc_hB[BQ * HQ];
__device__ float sc_c[BQ * HQ];
__device__ float sc_rv[BQ * WQ];
__device__ float sc_rw[BQ * NQ];
__device__ float sc_ww[BQ * NQ];
__device__ float sc_heads[BQ * HRP];
__device__ float sc_keys[2 * BQ * WQ];
__device__ float sc_beta[2 * BQ];
__device__ float sc_gamma[2 * BQ];
__device__ float sc_er[BQ * WQ];
__device__ float sc_ad[BQ * WQ];
__device__ float sc_sim[2 * BQ * NQ];
__device__ float sc_invn[NQ];
__device__ float sc_rvpart[NCHUNK * BQ * WQ];

// ---------------- helpers ----------------
__device__ __forceinline__ float sigmoidf_(float x) { return 1.0f / (1.0f + expf(-x)); }
__device__ __forceinline__ float softplusf_(float x) { return x > 20.0f ? x : log1pf(expf(x)); }

__device__ __forceinline__ float blockSum128(float v, float* sh) {
    #pragma unroll
    for (int o = 16; o; o >>= 1) v += __shfl_xor_sync(0xffffffffu, v, o);
    int wp = threadIdx.x >> 5;
    if ((threadIdx.x & 31) == 0) sh[wp] = v;
    __syncthreads();
    float r = sh[0] + sh[1] + sh[2] + sh[3];
    __syncthreads();
    return r;
}

// ---------------- prologue kernels ----------------
__global__ void k_build_wcat(const float* __restrict__ Wih, const float* __restrict__ Whh) {
    long long idx = (long long)blockIdx.x * blockDim.x + threadIdx.x;
    if (idx >= (long long)G4 * K1) return;
    int r = (int)(idx / K1), k = (int)(idx % K1);
    int j = r >> 2, g = r & 3;
    int src = g * HQ + j;
    sc_Wcat[idx] = (k < INQ + WQ) ? Wih[src * (INQ + WQ) + k] : Whh[src * HQ + (k - INQ - WQ)];
}

__global__ void k_build_bg(const float* __restrict__ bih, const float* __restrict__ bhh) {
    int r = blockIdx.x * blockDim.x + threadIdx.x;
    if (r >= G4) return;
    int j = r >> 2, g = r & 3;
    int src = g * HQ + j;
    sc_bg[r] = bih[src] + bhh[src];
}

__global__ void k_build_woutp(const float* __restrict__ Wout) {
    long long idx = (long long)blockIdx.x * blockDim.x + threadIdx.x;
    if (idx >= (long long)CP * HQ) return;
    int r = (int)(idx / HQ), k = (int)(idx % HQ);
    sc_WoutP[idx] = (r < CQ) ? Wout[(long long)r * HQ + k] : 0.0f;
}

__global__ void k_build_hw(const float* rkW, const float* rbW, const float* rgW,
                           const float* wkW, const float* wbW, const float* wgW,
                           const float* erW, const float* adW,
                           const float* rkb, const float* rbb, const float* rgb,
                           const float* wkb, const float* wbb, const float* wgb,
                           const float* erb, const float* adb) {
    int idx = blockIdx.x * blockDim.x + threadIdx.x;
    if (idx >= HRP * CP) return;
    int r = idx / CP, k = idx % CP;
    float wv = 0.0f, bv = 0.0f;
    if (k < CQ && r < 516) {
        if (r < 128)      { wv = rkW[r * CQ + k];         bv = rkb[r]; }
        else if (r == 128){ wv = rbW[k];                  bv = rbb[0]; }
        else if (r == 129){ wv = rgW[k];                  bv = rgb[0]; }
        else if (r < 258) { wv = wkW[(r - 130) * CQ + k]; bv = wkb[r - 130]; }
        else if (r == 258){ wv = wbW[k];                  bv = wbb[0]; }
        else if (r == 259){ wv = wgW[k];                  bv = wgb[0]; }
        else if (r < 388) { wv = erW[(r - 260) * CQ + k]; bv = erb[r - 260]; }
        else              { wv = adW[(r - 388) * CQ + k]; bv = adb[r - 388]; }
    }
    sc_HW[idx] = wv;
    if (k == 0) sc_Hb[r] = bv;
}

__global__ void k_init(const float* __restrict__ memory) {
    long long i = (long long)blockIdx.x * blockDim.x + threadIdx.x;
    long long tot = (long long)NQ * WQ;
    if (i < tot) {
        sc_mem[i] = memory[i];
        sc_rw[i]  = 1.0f / (float)NQ;
    }
    if (i < BQ * HQ) { sc_hA[i] = 0.0f; sc_hB[i] = 0.0f; sc_c[i] = 0.0f; }
    if (i < BQ * WQ) sc_rv[i] = 0.0f;
}

__global__ void k_invnorm() {
    int row = blockIdx.x * (blockDim.x >> 5) + (threadIdx.x >> 5);
    int lane = threadIdx.x & 31;
    if (row >= NQ) return;
    const float* r = sc_mem + (long long)row * WQ;
    float s = 0.f;
    #pragma unroll
    for (int i = 0; i < 4; i++) { float v = r[lane + 32 * i]; s += v * v; }
    #pragma unroll
    for (int o = 16; o; o >>= 1) s += __shfl_xor_sync(0xffffffffu, s, o);
    if (lane == 0) sc_invn[row] = 1.0f / fmaxf(sqrtf(s), 1e-12f);
}

// folded biases into sc_HOb
__global__ __launch_bounds__(128) void k_biases(const float* __restrict__ bout,
                                                const float* __restrict__ pW,
                                                const float* __restrict__ pb) {
    __shared__ float sh[4];
    int r = blockIdx.x, t = threadIdx.x;
    float s = 0.f;
    if (r < HRP) {
        for (int c = t; c < CQ; c += 128) s += sc_HW[r * CP + c] * bout[c];
        s = blockSum128(s, sh);
        if (t == 0) sc_HOb[r] = s + sc_Hb[r];
    } else {
        int o = r - HRP;
        for (int c = t; c < OUTQ; c += 128) s += pW[o * OUTQ + c] * bout[c];
        s = blockSum128(s, sh);
        if (t == 0) sc_HOb[r] = s + pb[o];
    }
}

// C[M,N] = A[M,K] @ B[K,N]  (32x32 tiles)
__global__ __launch_bounds__(256) void sgemm_nn32(
    const float* __restrict__ A, int lda,
    const float* __restrict__ B, int ldb,
    float* __restrict__ C, int ldc, int K)
{
    __shared__ float As[32][36];
    __shared__ float Bs[32][36];
    int tid = threadIdx.x;
    int n0 = blockIdx.x * 32, m0 = blockIdx.y * 32;
    int rowL = tid >> 3, k4 = (tid & 7) * 4;
    int tm = tid & 7, tn = tid >> 3;
    float acc[4] = {};
    for (int k0 = 0; k0 < K; k0 += 32) {
        float4 a = *(const float4*)(A + (long long)(m0 + rowL) * lda + k0 + k4);
        As[rowL][k4 + 0] = a.x; As[rowL][k4 + 1] = a.y; As[rowL][k4 + 2] = a.z; As[rowL][k4 + 3] = a.w;
        float4 b = *(const float4*)(B + (long long)(k0 + rowL) * ldb + n0 + k4);
        Bs[rowL][k4 + 0] = b.x; Bs[rowL][k4 + 1] = b.y; Bs[rowL][k4 + 2] = b.z; Bs[rowL][k4 + 3] = b.w;
        __syncthreads();
        #pragma unroll
        for (int k = 0; k < 32; k++) {
            float bv = Bs[k][tn];
            #pragma unroll
            for (int i = 0; i < 4; i++)
                acc[i] = fmaf(As[tm * 4 + i][k], bv, acc[i]);
        }
        __syncthreads();
    }
    #pragma unroll
    for (int i = 0; i < 4; i++)
        C[(long long)(m0 + tm * 4 + i) * ldc + n0 + tn] = acc[i];
}

// xg = x @ Wih_x^T for all steps (prologue)
__global__ __launch_bounds__(256) void k_xg(const float* __restrict__ x) {
    __shared__ float As[16][68];
    __shared__ float Bs[16][68];
    int tid = threadIdx.x;
    int n0 = blockIdx.x * 64, m0 = blockIdx.y * 64;
    int rowL = tid >> 2, k4 = (tid & 3) * 4;
    int txm = tid & 15, txn = tid >> 4;
    float acc[4][4] = {};
    int m = m0 + rowL;
    int s_ = m >> 7, b_ = m & 127;
    const float* arow = x + ((long long)b_ * SQ + s_) * INQ;
    const float* brow = sc_Wcat + (long long)(n0 + rowL) * K1;
    for (int k0 = 0; k0 < INQ; k0 += 16) {
        float4 a = *(const float4*)(arow + k0 + k4);
        float4 b = *(const float4*)(brow + k0 + k4);
        As[k4 + 0][rowL] = a.x; As[k4 + 1][rowL] = a.y; As[k4 + 2][rowL] = a.z; As[k4 + 3][rowL] = a.w;
        Bs[k4 + 0][rowL] = b.x; Bs[k4 + 1][rowL] = b.y; Bs[k4 + 2][rowL] = b.z; Bs[k4 + 3][rowL] = b.w;
        __syncthreads();
        #pragma unroll
        for (int k = 0; k < 16; k++) {
            float4 av = *(const float4*)&As[k][txm * 4];
            float4 bv = *(const float4*)&Bs[k][txn * 4];
            float aa[4] = {av.x, av.y, av.z, av.w};
            float bb[4] = {bv.x, bv.y, bv.z, bv.w};
            #pragma unroll
            for (int i = 0; i < 4; i++)
                #pragma unroll
                for (int j = 0; j < 4; j++)
                    acc[i][j] = fmaf(aa[i], bb[j], acc[i][j]);
        }
        __syncthreads();
    }
    #pragma unroll
    for (int i = 0; i < 4; i++) {
        long long mi = m0 + txm * 4 + i;
        #pragma unroll
        for (int j = 0; j < 4; j++)
            sc_xg[mi * G4 + n0 + txn * 4 + j] = acc[i][j];
    }
}

// ---------------- per-step kernels ----------------
// split-K recurrent GEMM: partial[ks] = [rv|h] @ Wcat_rec^T (K-slice ks)
__global__ __launch_bounds__(256) void k_lstm_part(const float* __restrict__ hprev) {
    __shared__ float As[16][68];
    __shared__ float Bs[16][68];
    int tid = threadIdx.x;
    int n0 = blockIdx.x * 64, m0 = blockIdx.y * 64;
    int ks = blockIdx.z;
    int rowL = tid >> 2, k4 = (tid & 3) * 4;
    int txm = tid & 15, txn = tid >> 4;
    float acc[4][4] = {};
    const float* brow = sc_Wcat + (long long)(n0 + rowL) * K1 + INQ + ks * KSL;
    for (int k0 = 0; k0 < KSL; k0 += 16) {
        int kg = ks * KSL + k0 + k4;
        const float* ap = (kg < WQ) ? (sc_rv + (m0 + rowL) * WQ + kg)
                                    : (hprev + (m0 + rowL) * HQ + (kg - WQ));
        float4 a = *(const float4*)ap;
        float4 b = *(const float4*)(brow + k0 + k4);
        As[k4 + 0][rowL] = a.x; As[k4 + 1][rowL] = a.y; As[k4 + 2][rowL] = a.z; As[k4 + 3][rowL] = a.w;
        Bs[k4 + 0][rowL] = b.x; Bs[k4 + 1][rowL] = b.y; Bs[k4 + 2][rowL] = b.z; Bs[k4 + 3][rowL] = b.w;
        __syncthreads();
        #pragma unroll
        for (int k = 0; k < 16; k++) {
            float4 av = *(const float4*)&As[k][txm * 4];
            float4 bv = *(const float4*)&Bs[k][txn * 4];
            float aa[4] = {av.x, av.y, av.z, av.w};
            float bb[4] = {bv.x, bv.y, bv.z, bv.w};
            #pragma unroll
            for (int i = 0; i < 4; i++)
                #pragma unroll
                for (int j = 0; j < 4; j++)
                    acc[i][j] = fmaf(aa[i], bb[j], acc[i][j]);
        }
        __syncthreads();
    }
    float* dst = sc_g3 + (long long)ks * BQ * G4;
    #pragma unroll
    for (int i = 0; i < 4; i++) {
        long long mi = m0 + txm * 4 + i;
        *(float4*)&dst[mi * G4 + n0 + txn * 4] = make_float4(acc[i][0], acc[i][1], acc[i][2], acc[i][3]);
    }
}

// gates reduce: sum 3 partials + xg + bias -> c, h  (one thread per (b,unit))
__global__ __launch_bounds__(256) void k_gates(int s, float* __restrict__ hnext) {
    int idx = blockIdx.x * blockDim.x + threadIdx.x;
    if (idx >= BQ * HQ) return;
    int b = idx >> 10, u = idx & 1023;
    long long off = (long long)b * G4 + u * 4;
    float4 p0 = *(const float4*)&sc_g3[off];
    float4 p1 = *(const float4*)&sc_g3[(long long)BQ * G4 + off];
    float4 p2 = *(const float4*)&sc_g3[(long long)2 * BQ * G4 + off];
    float4 xg = *(const float4*)&sc_xg[((long long)s * BQ + b) * G4 + u * 4];
    float4 bg = *(const float4*)&sc_bg[u * 4];
    float i_ = p0.x + p1.x + p2.x + xg.x + bg.x;
    float f_ = p0.y + p1.y + p2.y + xg.y + bg.y;
    float g_ = p0.z + p1.z + p2.z + xg.z + bg.z;
    float o_ = p0.w + p1.w + p2.w + xg.w + bg.w;
    float c = sigmoidf_(f_) * sc_c[idx] + sigmoidf_(i_) * tanhf(g_);
    sc_c[idx] = c;
    hnext[idx] = sigmoidf_(o_) * tanhf(c);
}

// merged heads+out GEMM: [128 x 1088] = h @ HOW^T + HOb; cols<576 -> sc_heads, else -> out
__global__ __launch_bounds__(256) void k_headsout(const float* __restrict__ A,
                                                  float* __restrict__ out, int s) {
    __shared__ float As[32][33];
    __shared__ float Bs[32][33];
    int tid = threadIdx.x;
    int n0 = blockIdx.x * 32, m0 = blockIdx.y * 32;
    int rowL = tid >> 3, k4 = (tid & 7) * 4;
    int tm = tid & 7, tn = tid >> 3;
    float acc[4] = {};
    for (int k0 = 0; k0 < HQ; k0 += 32) {
        float4 a = *(const float4*)(A + (long long)(m0 + rowL) * HQ + k0 + k4);
        float4 b = *(const float4*)(sc_HOW + (long long)(n0 + rowL) * HQ + k0 + k4);
        As[rowL][k4 + 0] = a.x; As[rowL][k4 + 1] = a.y; As[rowL][k4 + 2] = a.z; As[rowL][k4 + 3] = a.w;
        Bs[rowL][k4 + 0] = b.x; Bs[rowL][k4 + 1] = b.y; Bs[rowL][k4 + 2] = b.z; Bs[rowL][k4 + 3] = b.w;
        __syncthreads();
        #pragma unroll
        for (int k = 0; k < 32; k++) {
            float bv = Bs[tn][k];
            #pragma unroll
            for (int i = 0; i < 4; i++)
                acc[i] = fmaf(As[tm * 4 + i][k], bv, acc[i]);
        }
        __syncthreads();
    }
    int n = n0 + tn;
    float bb = sc_HOb[n];
    #pragma unroll
    for (int i = 0; i < 4; i++) {
        int m = m0 + tm * 4 + i;
        float v = acc[i] + bb;
        if (n < HRP) sc_heads[m * HRP + n] = v;
        else         out[((long long)m * SQ + s) * OUTQ + (n - HRP)] = v;
    }
}

__global__ __launch_bounds__(128) void k_headproc() {
    __shared__ float sh[4];
    int b = blockIdx.x, w = threadIdx.x;
    const float* hd = sc_heads + b * HRP;
    float rk = hd[w], wk = hd[130 + w];
    float nr2 = blockSum128(rk * rk, sh);
    float nw2 = blockSum128(wk * wk, sh);
    sc_keys[b * WQ + w]         = rk / fmaxf(sqrtf(nr2), 1e-12f);
    sc_keys[(128 + b) * WQ + w] = wk / fmaxf(sqrtf(nw2), 1e-12f);
    if (w == 0) {
        sc_beta[b]        = softplusf_(hd[128]);
        sc_gamma[b]       = 1.0f + softplusf_(hd[129]);
        sc_beta[128 + b]  = softplusf_(hd[258]);
        sc_gamma[128 + b] = 1.0f + softplusf_(hd[259]);
    }
    sc_er[b * WQ + w] = sigmoidf_(hd[260 + w]);
    sc_ad[b * WQ + w] = tanhf(hd[388 + w]);
}

// sim = keys @ mem^T * invn[n]
__global__ __launch_bounds__(256) void k_sim() {
    __shared__ float As[16][68];
    __shared__ float Bs[16][68];
    int tid = threadIdx.x;
    int n0 = blockIdx.x * 64, m0 = blockIdx.y * 64;
    int rowL = tid >> 2, k4 = (tid & 3) * 4;
    int txm = tid & 15, txn = tid >> 4;
    float acc[4][4] = {};
    const float* arow = sc_keys + (long long)(m0 + rowL) * WQ;
    const float* brow = sc_mem + (long long)(n0 + rowL) * WQ;
    for (int k0 = 0; k0 < WQ; k0 += 16) {
        float4 a = *(const float4*)(arow + k0 + k4);
        float4 b = *(const float4*)(brow + k0 + k4);
        As[k4 + 0][rowL] = a.x; As[k4 + 1][rowL] = a.y; As[k4 + 2][rowL] = a.z; As[k4 + 3][rowL] = a.w;
        Bs[k4 + 0][rowL] = b.x; Bs[k4 + 1][rowL] = b.y; Bs[k4 + 2][rowL] = b.z; Bs[k4 + 3][rowL] = b.w;
        __syncthreads();
        #pragma unroll
        for (int k = 0; k < 16; k++) {
            float4 av = *(const float4*)&As[k][txm * 4];
            float4 bv = *(const float4*)&Bs[k][txn * 4];
            float aa[4] = {av.x, av.y, av.z, av.w};
            float bb[4] = {bv.x, bv.y, bv.z, bv.w};
            #pragma unroll
            for (int i = 0; i < 4; i++)
                #pragma unroll
                for (int j = 0; j < 4; j++)
                    acc[i][j] = fmaf(aa[i], bb[j], acc[i][j]);
        }
        __syncthreads();
    }
    float4 cs = *(const float4*)&sc_invn[n0 + txn * 4];
    float csv[4] = {cs.x, cs.y, cs.z, cs.w};
    #pragma unroll
    for (int i = 0; i < 4; i++) {
        long long m = m0 + txm * 4 + i;
        #pragma unroll
        for (int j = 0; j < 4; j++)
            sc_sim[m * NQ + n0 + txn * 4 + j] = acc[i][j] * csv[j];
    }
}

// register-resident softmax + interpolation
__global__ __launch_bounds__(512) void k_softmax512() {
    __shared__ float sh[16];
    __shared__ float bcv;
    int q = blockIdx.x, tid = threadIdx.x;
    int lane = tid & 31, wid = tid >> 5;
    float beta = sc_beta[q], gamma = sc_gamma[q];
    const float* row = sc_sim + (long long)q * NQ;
    float v[32];
    float mx = -1e30f;
    #pragma unroll
    for (int i = 0; i < 32; i++) { v[i] = row[tid + i * 512]; mx = fmaxf(mx, v[i]); }
    #pragma unroll
    for (int o = 16; o; o >>= 1) mx = fmaxf(mx, __shfl_xor_sync(0xffffffffu, mx, o));
    if (lane == 0) sh[wid] = mx;
    __syncthreads();
    if (tid == 0) {
        float m = sh[0];
        #pragma unroll
        for (int i = 1; i < 16; i++) m = fmaxf(m, sh[i]);
        bcv = m;
    }
    __syncthreads();
    mx = bcv;
    float s = 0.f;
    #pragma unroll
    for (int i = 0; i < 32; i++) { v[i] = __expf(beta * (v[i] - mx)); s += v[i]; }
    __syncthreads();
    #pragma unroll
    for (int o = 16; o; o >>= 1) s += __shfl_xor_sync(0xffffffffu, s, o);
    if (lane == 0) sh[wid] = s;
    __syncthreads();
    if (tid == 0) {
        float t = 0.f;
        #pragma unroll
        for (int i = 0; i < 16; i++) t += sh[i];
        bcv = 1.0f / t;
    }
    __syncthreads();
    float inv = bcv;
    if (q < 128) {
        float* rw = sc_rw + (long long)q * NQ;
        #pragma unroll
        for (int i = 0; i < 32; i++) {
            int n = tid + i * 512;
            rw[n] = gamma * (v[i] * inv) + (1.0f - gamma) * rw[n];
        }
    } else {
        float* ww = sc_ww + (long long)(q - 128) * NQ;
        float u = (1.0f - gamma) * (1.0f / (float)NQ);
        #pragma unroll
        for (int i = 0; i < 32; i++)
            ww[tid + i * 512] = gamma * (v[i] * inv) + u;
    }
}

// fused: memory erase/add + next-step invnorm + rv split-K partials
__global__ __launch_bounds__(256) void k_memupd_rv() {
    __shared__ __align__(16) float mns[64][132];
    __shared__ __align__(16) float ubuf[2656];
    __shared__ float rowsq[64][4];
    float (*sw)[68]   = (float(*)[68])ubuf;
    float (*se)[132]  = (float(*)[132])(ubuf + 8 * 68);
    float (*sa)[132]  = (float(*)[132])(ubuf + 8 * 68 + 8 * 132);
    float (*srw)[132] = (float(*)[132])ubuf;
    int tid = threadIdx.x;
    int n0 = blockIdx.x * 64;
    int txn = tid & 15, txw = tid >> 4;
    float ae[4][8] = {}, aa[4][8] = {};
    for (int b0 = 0; b0 < BQ; b0 += 8) {
        {
            int kk = tid >> 5, half = tid & 31;
            *(float2*)&sw[kk][half * 2] = *(const float2*)&sc_ww[(long long)(b0 + kk) * NQ + n0 + half * 2];
            *(float4*)&se[kk][half * 4] = *(const float4*)&sc_er[(b0 + kk) * WQ + half * 4];
            *(float4*)&sa[kk][half * 4] = *(const float4*)&sc_ad[(b0 + kk) * WQ + half * 4];
        }
        __syncthreads();
        #pragma unroll
        for (int k = 0; k < 8; k++) {
            float4 w4 = *(const float4*)&sw[k][txn * 4];
            float4 e0 = *(const float4*)&se[k][txw * 8];
            float4 e1 = *(const float4*)&se[k][txw * 8 + 4];
            float4 a0 = *(const float4*)&sa[k][txw * 8];
            float4 a1 = *(const float4*)&sa[k][txw * 8 + 4];
            float wv[4] = {w4.x, w4.y, w4.z, w4.w};
            float ev[8] = {e0.x, e0.y, e0.z, e0.w, e1.x, e1.y, e1.z, e1.w};
            float av[8] = {a0.x, a0.y, a0.z, a0.w, a1.x, a1.y, a1.z, a1.w};
            #pragma unroll
            for (int i = 0; i < 4; i++)
                #pragma unroll
                for (int j = 0; j < 8; j++) {
                    ae[i][j] = fmaf(wv[i], ev[j], ae[i][j]);
                    aa[i][j] = fmaf(wv[i], av[j], aa[i][j]);
                }
        }
        __syncthreads();
    }
    #pragma unroll
    for (int i = 0; i < 4; i++) {
        int nl = txn * 4 + i;
        long long base = (long long)(n0 + nl) * WQ + txw * 8;
        float4 m0v = *(const float4*)&sc_mem[base];
        float4 m1v = *(const float4*)&sc_mem[base + 4];
        float r[8] = {m0v.x, m0v.y, m0v.z, m0v.w, m1v.x, m1v.y, m1v.z, m1v.w};
        #pragma unroll
        for (int j = 0; j < 8; j++) r[j] = r[j] * (1.0f - ae[i][j]) + aa[i][j];
        *(float4*)&sc_mem[base]     = make_float4(r[0], r[1], r[2], r[3]);
        *(float4*)&sc_mem[base + 4] = make_float4(r[4], r[5], r[6], r[7]);
        *(float4*)&mns[nl][txw * 8]     = make_float4(r[0], r[1], r[2], r[3]);
        *(float4*)&mns[nl][txw * 8 + 4] = make_float4(r[4], r[5], r[6], r[7]);
    }
    __syncthreads();
    {
        int r = tid >> 2, qq = tid & 3;
        float s = 0.f;
        #pragma unroll
        for (int t = 0; t < 32; t += 4) {
            float4 v = *(const float4*)&mns[r][qq * 32 + t];
            s += v.x * v.x + v.y * v.y + v.z * v.z + v.w * v.w;
        }
        rowsq[r][qq] = s;
    }
    __syncthreads();
    if (tid < 64) {
        float s = rowsq[tid][0] + rowsq[tid][1] + rowsq[tid][2] + rowsq[tid][3];
        sc_invn[n0 + tid] = 1.0f / fmaxf(sqrtf(s), 1e-12f);
    }
    int tb = tid & 15, tw = tid >> 4;
    float racc[8][8] = {};
    for (int nc = 0; nc < 4; nc++) {
        __syncthreads();
        #pragma unroll
        for (int r = 0; r < 8; r++) {
            int b = (tid >> 4) + r * 16, nn = tid & 15;
            srw[nn][b] = sc_rw[(long long)b * NQ + n0 + nc * 16 + nn];
        }
        __syncthreads();
        #pragma unroll
        for (int nn = 0; nn < 16; nn++) {
            float4 r0 = *(const float4*)&srw[nn][tb * 8];
            float4 r1 = *(const float4*)&srw[nn][tb * 8 + 4];
            int nl = nc * 16 + nn;
            float4 q0 = *(const float4*)&mns[nl][tw * 8];
            float4 q1 = *(const float4*)&mns[nl][tw * 8 + 4];
            float rb[8] = {r0.x, r0.y, r0.z, r0.w, r1.x, r1.y, r1.z, r1.w};
            float mw[8] = {q0.x, q0.y, q0.z, q0.w, q1.x, q1.y, q1.z, q1.w};
            #pragma unroll
            for (int i = 0; i < 8; i++)
                #pragma unroll
                for (int j = 0; j < 8; j++)
                    racc[i][j] = fmaf(rb[i], mw[j], racc[i][j]);
        }
    }
    float* dst = sc_rvpart + (long long)blockIdx.x * BQ * WQ;
    #pragma unroll
    for (int i = 0; i < 8; i++) {
        int b = tb * 8 + i;
        *(float4*)&dst[b * WQ + tw * 8]     = make_float4(racc[i][0], racc[i][1], racc[i][2], racc[i][3]);
        *(float4*)&dst[b * WQ + tw * 8 + 4] = make_float4(racc[i][4], racc[i][5], racc[i][6], racc[i][7]);
    }
}

// parallel deterministic reduce: 128 blocks, 8 threads/output x 32 chunks each
__global__ __launch_bounds__(256) void k_rvreduce() {
    __shared__ float4 red[32][8];
    int tid = threadIdx.x;
    int outIdx = blockIdx.x * 32 + (tid >> 3);
    int sub = tid & 7;
    const float4* p = (const float4*)sc_rvpart;
    float4 s = make_float4(0.f, 0.f, 0.f, 0.f);
    #pragma unroll 4
    for (int i = 0; i < 32; i++) {
        float4 t = p[(long long)(sub + i * 8) * 4096 + outIdx];
        s.x += t.x; s.y += t.y; s.z += t.z; s.w += t.w;
    }
    red[tid >> 3][sub] = s;
    __syncthreads();
    if (sub == 0) {
        float4 a = make_float4(0.f, 0.f, 0.f, 0.f);
        #pragma unroll
        for (int i = 0; i < 8; i++) {
            float4 t = red[tid >> 3][i];
            a.x += t.x; a.y += t.y; a.z += t.z; a.w += t.w;
        }
        ((float4*)sc_rv)[outIdx] = a;
    }
}

// ---------------- host launcher ----------------
extern "C" void kernel_launch(void* const* d_in, const int* in_sizes, int n_in,
                              void* d_out, int out_size) {
    const float* x      = (const float*)d_in[0];
    const float* memory = (const float*)d_in[1];
    const float* Wih    = (const float*)d_in[2];
    const float* Whh    = (const float*)d_in[3];
    const float* bih    = (const float*)d_in[4];
    const float* bhh    = (const float*)d_in[5];
    const float* Wout   = (const float*)d_in[6];
    const float* bout   = (const float*)d_in[7];
    const float* rkW    = (const float*)d_in[8];
    const float* rkb    = (const float*)d_in[9];
    const float* rbW    = (const float*)d_in[10];
    const float* rbb    = (const float*)d_in[11];
    const float* rgW    = (const float*)d_in[12];
    const float* rgb    = (const float*)d_in[13];
    const float* wkW    = (const float*)d_in[14];
    const float* wkb    = (const float*)d_in[15];
    const float* wbW    = (const float*)d_in[16];
    const float* wbb    = (const float*)d_in[17];
    const float* wgW    = (const float*)d_in[18];
    const float* wgb    = (const float*)d_in[19];
    const float* erW    = (const float*)d_in[20];
    const float* erb    = (const float*)d_in[21];
    const float* adW    = (const float*)d_in[22];
    const float* adb    = (const float*)d_in[23];
    const float* pW     = (const float*)d_in[24];
    const float* pb     = (const float*)d_in[25];
    float* out          = (float*)d_out;

    float *phA, *phB, *pHW, *pHOW, *pWoutP;
    cudaGetSymbolAddress((void**)&phA,    sc_hA);
    cudaGetSymbolAddress((void**)&phB,    sc_hB);
    cudaGetSymbolAddress((void**)&pHW,    sc_HW);
    cudaGetSymbolAddress((void**)&pHOW,   sc_HOW);
    cudaGetSymbolAddress((void**)&pWoutP, sc_WoutP);

    // ---- prologue ----
    k_build_wcat<<<(int)(((long long)G4 * K1 + 255) / 256), 256>>>(Wih, Whh);
    k_build_bg<<<(G4 + 255) / 256, 256>>>(bih, bhh);
    k_build_woutp<<<(int)(((long long)CP * HQ + 255) / 256), 256>>>(Wout);
    k_build_hw<<<(HRP * CP + 255) / 256, 256>>>(rkW, rbW, rgW, wkW, wbW, wgW, erW, adW,
                                                rkb, rbb, rgb, wkb, wbb, wgb, erb, adb);
    k_init<<<(int)(((long long)NQ * WQ + 511) / 512), 512>>>(memory);
    k_invnorm<<<NQ / 8, 256>>>();
    k_xg<<<dim3(G4 / 64, MQ / 64), 256>>>(x);
    // HOW rows 0..575 = HW @ WoutP
    sgemm_nn32<<<dim3(HQ / 32, HRP / 32), 256>>>(pHW, CP, pWoutP, HQ, pHOW, HQ, CP);
    // HOW rows 576..1087 = pW @ Wout[:512]
    sgemm_nn32<<<dim3(HQ / 32, OUTQ / 32), 256>>>(pW, OUTQ, Wout, HQ, pHOW + (long long)HRP * HQ, HQ, OUTQ);
    k_biases<<<HRP + OUTQ, 128>>>(bout, pW, pb);

    // ---- timestep loop ----
    for (int s = 0; s < SQ; s++) {
        float* hprev = (s & 1) ? phB : phA;
        float* hnext = (s & 1) ? phA : phB;
        k_lstm_part<<<dim3(G4 / 64, BQ / 64, 3), 256>>>(hprev);
        k_gates<<<(BQ * HQ + 255) / 256, 256>>>(s, hnext);
        k_headsout<<<dim3(HOW / 32, BQ / 32), 256>>>(hnext, out, s);
        k_headproc<<<BQ, 128>>>();
        k_sim<<<dim3(NQ / 64, 2 * BQ / 64), 256>>>();
        k_softmax512<<<2 * BQ, 512>>>();
        k_memupd_rv<<<NQ / 64, 256>>>();
        k_rvreduce<<<128, 256>>>();
    }
}